// round 2
// baseline (speedup 1.0000x reference)
#include <cuda_runtime.h>
#include <cuda_bf16.h>
#include <cstdint>

#define NN    50000
#define EE    800000
#define IN_F  128
#define OUT_F 64
#define NH    4
#define HO    256   // NH*OUT_F
#define NEG_SLOPE 0.2f
#define BN_EPS 1e-5f

// ---------------- scratch (device globals; zero-initialized at load, kept
// zeroed by self-cleaning consumers so every launch/replay sees clean state) --
__device__ float        g_h     [(size_t)NN * HO];     // node_feats @ W_fc
__device__ float        g_gres  [(size_t)NN * HO];     // node_feats @ gat_res_w
__device__ float        g_unnorm[(size_t)NN * HO];     // sum_e a*h[src]  (self-cleaned)
__device__ float        g_y0    [(size_t)NN * OUT_F];  // relu(node@res_w + res_b)
__device__ float        g_ybuf  [(size_t)NN * OUT_F];  // pre-BN y
__device__ float        g_e     [(size_t)EE * NH];     // per-edge logits
__device__ float        g_el    [NN * NH];
__device__ float        g_er    [NN * NH];
__device__ float        g_ssum  [NN * NH];             // self-cleaned
__device__ unsigned int g_mkey  [NN * NH];             // ordered-uint max keys, 0 = empty (self-cleaned)
__device__ float        g_bnsum [OUT_F];               // self-cleaned
__device__ float        g_bnsq  [OUT_F];               // self-cleaned
__device__ float        g_scale [OUT_F];
__device__ float        g_shift [OUT_F];

// ---------------- ordered float<->uint encoding for atomicMax ---------------
__device__ __forceinline__ unsigned int f2u_ord(float f) {
    int i = __float_as_int(f);
    i = (i >= 0) ? i : (i ^ 0x7fffffff);
    return (unsigned int)i + 0x80000000u;
}
__device__ __forceinline__ float u2f_ord(unsigned int u) {
    int i = (int)(u - 0x80000000u);
    i = (i >= 0) ? i : (i ^ 0x7fffffff);
    return __int_as_float(i);
}

// ---------------- Kernel 1: three GEMMs in one (col-tile selects weight) ----
// grid.x = ceil(NN/64), grid.y = 9 (0-3 W_fc, 4-7 gat_res_w, 8 res_w), 256 thr
__global__ void gemm_kernel(const float* __restrict__ A,
                            const float* __restrict__ Wfc,
                            const float* __restrict__ Wgres,
                            const float* __restrict__ Wres,
                            const float* __restrict__ res_b)
{
    const int ct = blockIdx.y;
    const float* B;
    int ldb, colbase, mode;
    if (ct < 4)      { B = Wfc;   ldb = HO;    colbase = ct * 64;       mode = 0; }
    else if (ct < 8) { B = Wgres; ldb = HO;    colbase = (ct - 4) * 64; mode = 1; }
    else             { B = Wres;  ldb = OUT_F; colbase = 0;             mode = 2; }

    __shared__ float As[32][68];  // transposed: [k][m]
    __shared__ float Bs[32][68];  // [k][n]

    const int row0 = blockIdx.x * 64;
    const int tx = threadIdx.x & 15;
    const int ty = threadIdx.x >> 4;

    float acc[4][4];
#pragma unroll
    for (int i = 0; i < 4; i++)
#pragma unroll
        for (int j = 0; j < 4; j++) acc[i][j] = 0.f;

    for (int k0 = 0; k0 < IN_F; k0 += 32) {
        // load A tile (64 rows x 32 k), transposed into As
        {
            int t = threadIdx.x;
            int r  = t >> 2;          // 0..63
            int kq = (t & 3) * 8;     // 0,8,16,24
            int grow = row0 + r;
            float4 v0, v1;
            if (grow < NN) {
                const float4* ap = reinterpret_cast<const float4*>(A + (size_t)grow * IN_F + k0 + kq);
                v0 = ap[0]; v1 = ap[1];
            } else {
                v0 = make_float4(0.f, 0.f, 0.f, 0.f); v1 = v0;
            }
            As[kq + 0][r] = v0.x; As[kq + 1][r] = v0.y; As[kq + 2][r] = v0.z; As[kq + 3][r] = v0.w;
            As[kq + 4][r] = v1.x; As[kq + 5][r] = v1.y; As[kq + 6][r] = v1.z; As[kq + 7][r] = v1.w;

            // load B tile (32 k x 64 cols)
            int kr = t >> 3;          // 0..31
            int cq = (t & 7) * 8;     // 0..56
            const float4* bp = reinterpret_cast<const float4*>(B + (size_t)(k0 + kr) * ldb + colbase + cq);
            float4 b0 = bp[0], b1 = bp[1];
            *reinterpret_cast<float4*>(&Bs[kr][cq])     = b0;
            *reinterpret_cast<float4*>(&Bs[kr][cq + 4]) = b1;
        }
        __syncthreads();

#pragma unroll
        for (int kk = 0; kk < 32; kk++) {
            float4 av = *reinterpret_cast<const float4*>(&As[kk][ty * 4]);
            float4 bv = *reinterpret_cast<const float4*>(&Bs[kk][tx * 4]);
            float a[4] = {av.x, av.y, av.z, av.w};
            float b[4] = {bv.x, bv.y, bv.z, bv.w};
#pragma unroll
            for (int i = 0; i < 4; i++)
#pragma unroll
                for (int j = 0; j < 4; j++) acc[i][j] += a[i] * b[j];
        }
        __syncthreads();
    }

#pragma unroll
    for (int i = 0; i < 4; i++) {
        int grow = row0 + ty * 4 + i;
        if (grow >= NN) continue;
#pragma unroll
        for (int j = 0; j < 4; j++) {
            int gcol = colbase + tx * 4 + j;
            float v = acc[i][j];
            if (mode == 0)      g_h   [(size_t)grow * HO + gcol] = v;
            else if (mode == 1) g_gres[(size_t)grow * HO + gcol] = v;
            else                g_y0  [(size_t)grow * OUT_F + gcol] = fmaxf(v + res_b[gcol], 0.f);
        }
    }
}

// ---------------- Kernel 2: el/er per (node, head) ---------------------------
__global__ void elr_kernel(const float* __restrict__ attn_l,
                           const float* __restrict__ attn_r)
{
    int t = blockIdx.x * blockDim.x + threadIdx.x;  // n*4 + h
    if (t >= NN * NH) return;
    int h = t & 3;
    const float4* hp = reinterpret_cast<const float4*>(g_h + (size_t)t * OUT_F);
    const float4* lp = reinterpret_cast<const float4*>(attn_l + h * OUT_F);
    const float4* rp = reinterpret_cast<const float4*>(attn_r + h * OUT_F);
    float el = 0.f, er = 0.f;
#pragma unroll
    for (int j = 0; j < OUT_F / 4; j++) {
        float4 hv = hp[j], lv = lp[j], rv = rp[j];
        el += hv.x * lv.x + hv.y * lv.y + hv.z * lv.z + hv.w * lv.w;
        er += hv.x * rv.x + hv.y * rv.y + hv.z * rv.z + hv.w * rv.w;
    }
    g_el[t] = el;
    g_er[t] = er;
}

// ---------------- Kernel 3: edge logits + segment max ------------------------
__global__ void edge_max_kernel(const int* __restrict__ src,
                                const int* __restrict__ dst)
{
    int e = blockIdx.x * blockDim.x + threadIdx.x;
    if (e >= EE) return;
    int s = src[e], d = dst[e];
#pragma unroll
    for (int h = 0; h < NH; h++) {
        float x = g_el[s * NH + h] + g_er[d * NH + h];
        x = (x >= 0.f) ? x : NEG_SLOPE * x;
        g_e[(size_t)e * NH + h] = x;
        atomicMax(&g_mkey[d * NH + h], f2u_ord(x));
    }
}

// ---------------- Kernel 4: exp + segment sum + UNNORMALIZED aggregation -----
// warp per edge: accumulate ssum[dst] and unnorm[dst] += a * h[src]
__global__ void edge_agg_kernel(const int* __restrict__ src,
                                const int* __restrict__ dst)
{
    int warp = (blockIdx.x * blockDim.x + threadIdx.x) >> 5;
    int lane = threadIdx.x & 31;
    if (warp >= EE) return;
    int s = src[warp], d = dst[warp];

    // all lanes compute all 4 head weights (scalar regs, no local-mem arrays)
    float a0, a1, a2, a3;
    {
        const float4 ev = *reinterpret_cast<const float4*>(g_e + (size_t)warp * NH);
        unsigned int k0 = g_mkey[d * NH + 0];
        unsigned int k1 = g_mkey[d * NH + 1];
        unsigned int k2 = g_mkey[d * NH + 2];
        unsigned int k3 = g_mkey[d * NH + 3];
        a0 = __expf(ev.x - u2f_ord(k0));
        a1 = __expf(ev.y - u2f_ord(k1));
        a2 = __expf(ev.z - u2f_ord(k2));
        a3 = __expf(ev.w - u2f_ord(k3));
    }
    if (lane < NH) {
        float av = (lane == 0) ? a0 : (lane == 1) ? a1 : (lane == 2) ? a2 : a3;
        atomicAdd(&g_ssum[d * NH + lane], av);
    }

    const float4* hs = reinterpret_cast<const float4*>(g_h + (size_t)s * HO);
    float4*       un = reinterpret_cast<float4*>(g_unnorm + (size_t)d * HO);

    // it=0: float4 idx lane(0..31) -> heads 0,1 ; it=1: idx lane+32 -> heads 2,3
    float w0 = (lane < 16) ? a0 : a1;
    float w1 = (lane < 16) ? a2 : a3;
    {
        float4 hv = hs[lane];
        float x = hv.x * w0, y = hv.y * w0, z = hv.z * w0, w = hv.w * w0;
        asm volatile("red.global.add.v4.f32 [%0], {%1,%2,%3,%4};"
                     :: "l"(un + lane), "f"(x), "f"(y), "f"(z), "f"(w)
                     : "memory");
    }
    {
        float4 hv = hs[lane + 32];
        float x = hv.x * w1, y = hv.y * w1, z = hv.z * w1, w = hv.w * w1;
        asm volatile("red.global.add.v4.f32 [%0], {%1,%2,%3,%4};"
                     :: "l"(un + lane + 32), "f"(x), "f"(y), "f"(z), "f"(w)
                     : "memory");
    }
}

// ---------------- Kernel 5: node epilogue (normalize, residuals, conv merge,
//                  BN partial stats); self-clean AFTER the block barrier -----
__global__ void node_final_kernel(const float* __restrict__ gat_bias,
                                  const float* __restrict__ conv_w,
                                  const float* __restrict__ conv_b)
{
    const int d = threadIdx.x;                          // 0..63
    const int n = blockIdx.x * blockDim.y + threadIdx.y;
    __shared__ float shs[8][64];
    __shared__ float shq[8][64];

    float y = 0.f;
    if (n < NN) {
        float acc = conv_b[0];
#pragma unroll
        for (int h = 0; h < NH; h++) {
            float ss = g_ssum[n * NH + h];
            size_t idx = (size_t)n * HO + h * OUT_F + d;
            float un = g_unnorm[idx];
            g_unnorm[idx] = 0.f;  // self-clean (own element, no race)
            float r = un / (ss + 1e-16f) + g_gres[idx] + gat_bias[h * OUT_F + d];
            r = fmaxf(r, 0.f);
            acc += r * conv_w[h];
        }
        y = acc + g_y0[(size_t)n * OUT_F + d];
        g_ybuf[(size_t)n * OUT_F + d] = y;
    }
    shs[threadIdx.y][d] = y;
    shq[threadIdx.y][d] = y * y;
    __syncthreads();   // ALL reads of g_ssum complete before any cleaning below
    if (n < NN && d < NH) {                // self-clean for next launch
        g_ssum[n * NH + d] = 0.f;
        g_mkey[n * NH + d] = 0u;
    }
    if (threadIdx.y == 0) {
        float sv = 0.f, qv = 0.f;
#pragma unroll
        for (int r = 0; r < 8; r++) { sv += shs[r][d]; qv += shq[r][d]; }
        atomicAdd(&g_bnsum[d], sv);
        atomicAdd(&g_bnsq[d],  qv);
    }
}

// ---------------- Kernel 6: BN stats -> scale/shift (+ self-clean) ----------
__global__ void bn_stats_kernel(const float* __restrict__ gamma,
                                const float* __restrict__ beta)
{
    int d = threadIdx.x;
    if (d >= OUT_F) return;
    float mean = g_bnsum[d] / (float)NN;
    float var  = g_bnsq[d] / (float)NN - mean * mean;
    float rstd = rsqrtf(var + BN_EPS);
    float sc = gamma[d] * rstd;
    g_scale[d] = sc;
    g_shift[d] = beta[d] - mean * sc;
    g_bnsum[d] = 0.f;   // self-clean
    g_bnsq[d]  = 0.f;
}

// ---------------- Kernel 7: normalize -> d_out -------------------------------
__global__ void bn_apply_kernel(float* __restrict__ out)
{
    int i = blockIdx.x * blockDim.x + threadIdx.x;
    if (i >= NN * OUT_F) return;
    int d = i & (OUT_F - 1);
    out[i] = g_ybuf[i] * g_scale[d] + g_shift[d];
}

// ---------------- launch -----------------------------------------------------
extern "C" void kernel_launch(void* const* d_in, const int* in_sizes, int n_in,
                              void* d_out, int out_size)
{
    const float* node_feats = (const float*)d_in[0];
    const float* W_fc       = (const float*)d_in[1];
    const float* attn_l     = (const float*)d_in[2];
    const float* attn_r     = (const float*)d_in[3];
    const float* gat_res_w  = (const float*)d_in[4];
    const float* gat_bias   = (const float*)d_in[5];
    const float* conv_w     = (const float*)d_in[6];
    const float* conv_b     = (const float*)d_in[7];
    const float* res_w      = (const float*)d_in[8];
    const float* res_b      = (const float*)d_in[9];
    const float* bn_gamma   = (const float*)d_in[10];
    const float* bn_beta    = (const float*)d_in[11];
    const int*   src        = (const int*)d_in[12];
    const int*   dst        = (const int*)d_in[13];
    float*       out        = (float*)d_out;

    // 1) the three GEMMs
    {
        dim3 grid((NN + 63) / 64, 9);
        gemm_kernel<<<grid, 256>>>(node_feats, W_fc, gat_res_w, res_w, res_b);
    }
    // 2) el / er
    {
        int total = NN * NH;
        elr_kernel<<<(total + 255) / 256, 256>>>(attn_l, attn_r);
    }
    // 3) edge logits + segment max
    edge_max_kernel<<<(EE + 255) / 256, 256>>>(src, dst);
    // 4) exp + segment sum + aggregation (warp per edge)
    {
        long long threads = (long long)EE * 32;
        edge_agg_kernel<<<(int)((threads + 255) / 256), 256>>>(src, dst);
    }
    // 5) node epilogue + BN partials
    {
        dim3 block(64, 8);
        node_final_kernel<<<(NN + 7) / 8, block>>>(gat_bias, conv_w, conv_b);
    }
    // 6) BN stats
    bn_stats_kernel<<<1, 64>>>(bn_gamma, bn_beta);
    // 7) normalize
    bn_apply_kernel<<<(NN * OUT_F + 255) / 256, 256>>>(out);
}

// round 3
// speedup vs baseline: 1.0021x; 1.0021x over previous
#include <cuda_runtime.h>
#include <cuda_bf16.h>
#include <cstdint>

#define NN    50000
#define EE    800000
#define IN_F  128
#define OUT_F 64
#define NH    4
#define HO    256   // NH*OUT_F
#define NEG_SLOPE 0.2f
#define BN_EPS 1e-5f

// ---------------- scratch (device globals; zero-initialized at load, kept
// zeroed by self-cleaning consumers so every launch/replay sees clean state) --
__device__ float        g_h     [(size_t)NN * HO];     // node_feats @ W_fc
__device__ float        g_gres  [(size_t)NN * HO];     // node_feats @ gat_res_w
__device__ float        g_unnorm[(size_t)NN * HO];     // sum_e a*h[src]  (self-cleaned)
__device__ float        g_y0    [(size_t)NN * OUT_F];  // relu(node@res_w + res_b)
__device__ float        g_ybuf  [(size_t)NN * OUT_F];  // pre-BN y
__device__ float        g_e     [(size_t)EE * NH];     // per-edge logits
__device__ float        g_el    [NN * NH];
__device__ float        g_er    [NN * NH];
__device__ float        g_ssum  [NN * NH];             // self-cleaned
__device__ unsigned int g_mkey  [NN * NH];             // ordered-uint max keys, 0 = empty (self-cleaned)
__device__ float        g_bnsum [OUT_F];               // self-cleaned
__device__ float        g_bnsq  [OUT_F];               // self-cleaned
__device__ float        g_scale [OUT_F];
__device__ float        g_shift [OUT_F];

// ---------------- ordered float<->uint encoding for atomicMax ---------------
__device__ __forceinline__ unsigned int f2u_ord(float f) {
    int i = __float_as_int(f);
    i = (i >= 0) ? i : (i ^ 0x7fffffff);
    return (unsigned int)i + 0x80000000u;
}
__device__ __forceinline__ float u2f_ord(unsigned int u) {
    int i = (int)(u - 0x80000000u);
    i = (i >= 0) ? i : (i ^ 0x7fffffff);
    return __int_as_float(i);
}

// ---------------- Kernel 1: three GEMMs in one (col-tile selects weight) ----
// grid.x = ceil(NN/64), grid.y = 9 (0-3 W_fc, 4-7 gat_res_w, 8 res_w), 256 thr
__global__ void gemm_kernel(const float* __restrict__ A,
                            const float* __restrict__ Wfc,
                            const float* __restrict__ Wgres,
                            const float* __restrict__ Wres,
                            const float* __restrict__ res_b)
{
    const int ct = blockIdx.y;
    const float* B;
    int ldb, colbase, mode;
    if (ct < 4)      { B = Wfc;   ldb = HO;    colbase = ct * 64;       mode = 0; }
    else if (ct < 8) { B = Wgres; ldb = HO;    colbase = (ct - 4) * 64; mode = 1; }
    else             { B = Wres;  ldb = OUT_F; colbase = 0;             mode = 2; }

    __shared__ float As[32][68];  // transposed: [k][m]
    __shared__ float Bs[32][68];  // [k][n]

    const int row0 = blockIdx.x * 64;
    const int tx = threadIdx.x & 15;
    const int ty = threadIdx.x >> 4;

    float acc[4][4];
#pragma unroll
    for (int i = 0; i < 4; i++)
#pragma unroll
        for (int j = 0; j < 4; j++) acc[i][j] = 0.f;

    for (int k0 = 0; k0 < IN_F; k0 += 32) {
        // load A tile (64 rows x 32 k), transposed into As
        {
            int t = threadIdx.x;
            int r  = t >> 2;          // 0..63
            int kq = (t & 3) * 8;     // 0,8,16,24
            int grow = row0 + r;
            float4 v0, v1;
            if (grow < NN) {
                const float4* ap = reinterpret_cast<const float4*>(A + (size_t)grow * IN_F + k0 + kq);
                v0 = ap[0]; v1 = ap[1];
            } else {
                v0 = make_float4(0.f, 0.f, 0.f, 0.f); v1 = v0;
            }
            As[kq + 0][r] = v0.x; As[kq + 1][r] = v0.y; As[kq + 2][r] = v0.z; As[kq + 3][r] = v0.w;
            As[kq + 4][r] = v1.x; As[kq + 5][r] = v1.y; As[kq + 6][r] = v1.z; As[kq + 7][r] = v1.w;

            // load B tile (32 k x 64 cols)
            int kr = t >> 3;          // 0..31
            int cq = (t & 7) * 8;     // 0..56
            const float4* bp = reinterpret_cast<const float4*>(B + (size_t)(k0 + kr) * ldb + colbase + cq);
            float4 b0 = bp[0], b1 = bp[1];
            *reinterpret_cast<float4*>(&Bs[kr][cq])     = b0;
            *reinterpret_cast<float4*>(&Bs[kr][cq + 4]) = b1;
        }
        __syncthreads();

#pragma unroll
        for (int kk = 0; kk < 32; kk++) {
            float4 av = *reinterpret_cast<const float4*>(&As[kk][ty * 4]);
            float4 bv = *reinterpret_cast<const float4*>(&Bs[kk][tx * 4]);
            float a[4] = {av.x, av.y, av.z, av.w};
            float b[4] = {bv.x, bv.y, bv.z, bv.w};
#pragma unroll
            for (int i = 0; i < 4; i++)
#pragma unroll
                for (int j = 0; j < 4; j++) acc[i][j] += a[i] * b[j];
        }
        __syncthreads();
    }

#pragma unroll
    for (int i = 0; i < 4; i++) {
        int grow = row0 + ty * 4 + i;
        if (grow >= NN) continue;
#pragma unroll
        for (int j = 0; j < 4; j++) {
            int gcol = colbase + tx * 4 + j;
            float v = acc[i][j];
            if (mode == 0)      g_h   [(size_t)grow * HO + gcol] = v;
            else if (mode == 1) g_gres[(size_t)grow * HO + gcol] = v;
            else                g_y0  [(size_t)grow * OUT_F + gcol] = fmaxf(v + res_b[gcol], 0.f);
        }
    }
}

// ---------------- Kernel 2: el/er per (node, head) ---------------------------
__global__ void elr_kernel(const float* __restrict__ attn_l,
                           const float* __restrict__ attn_r)
{
    int t = blockIdx.x * blockDim.x + threadIdx.x;  // n*4 + h
    if (t >= NN * NH) return;
    int h = t & 3;
    const float4* hp = reinterpret_cast<const float4*>(g_h + (size_t)t * OUT_F);
    const float4* lp = reinterpret_cast<const float4*>(attn_l + h * OUT_F);
    const float4* rp = reinterpret_cast<const float4*>(attn_r + h * OUT_F);
    float el = 0.f, er = 0.f;
#pragma unroll
    for (int j = 0; j < OUT_F / 4; j++) {
        float4 hv = hp[j], lv = lp[j], rv = rp[j];
        el += hv.x * lv.x + hv.y * lv.y + hv.z * lv.z + hv.w * lv.w;
        er += hv.x * rv.x + hv.y * rv.y + hv.z * rv.z + hv.w * rv.w;
    }
    g_el[t] = el;
    g_er[t] = er;
}

// ---------------- Kernel 3: edge logits + segment max ------------------------
__global__ void edge_max_kernel(const int* __restrict__ src,
                                const int* __restrict__ dst)
{
    int e = blockIdx.x * blockDim.x + threadIdx.x;
    if (e >= EE) return;
    int s = src[e], d = dst[e];
#pragma unroll
    for (int h = 0; h < NH; h++) {
        float x = g_el[s * NH + h] + g_er[d * NH + h];
        x = (x >= 0.f) ? x : NEG_SLOPE * x;
        g_e[(size_t)e * NH + h] = x;
        atomicMax(&g_mkey[d * NH + h], f2u_ord(x));
    }
}

// ---------------- Kernel 4: exp + segment sum + UNNORMALIZED aggregation -----
// warp per edge: accumulate ssum[dst] and unnorm[dst] += a * h[src]
__global__ void edge_agg_kernel(const int* __restrict__ src,
                                const int* __restrict__ dst)
{
    int warp = (blockIdx.x * blockDim.x + threadIdx.x) >> 5;
    int lane = threadIdx.x & 31;
    if (warp >= EE) return;
    int s = src[warp], d = dst[warp];

    // all lanes compute all 4 head weights (scalar regs, no local-mem arrays)
    float a0, a1, a2, a3;
    {
        const float4 ev = *reinterpret_cast<const float4*>(g_e + (size_t)warp * NH);
        unsigned int k0 = g_mkey[d * NH + 0];
        unsigned int k1 = g_mkey[d * NH + 1];
        unsigned int k2 = g_mkey[d * NH + 2];
        unsigned int k3 = g_mkey[d * NH + 3];
        a0 = __expf(ev.x - u2f_ord(k0));
        a1 = __expf(ev.y - u2f_ord(k1));
        a2 = __expf(ev.z - u2f_ord(k2));
        a3 = __expf(ev.w - u2f_ord(k3));
    }
    if (lane < NH) {
        float av = (lane == 0) ? a0 : (lane == 1) ? a1 : (lane == 2) ? a2 : a3;
        atomicAdd(&g_ssum[d * NH + lane], av);
    }

    const float4* hs = reinterpret_cast<const float4*>(g_h + (size_t)s * HO);
    float4*       un = reinterpret_cast<float4*>(g_unnorm + (size_t)d * HO);

    // it=0: float4 idx lane(0..31) -> heads 0,1 ; it=1: idx lane+32 -> heads 2,3
    float w0 = (lane < 16) ? a0 : a1;
    float w1 = (lane < 16) ? a2 : a3;
    {
        float4 hv = hs[lane];
        float x = hv.x * w0, y = hv.y * w0, z = hv.z * w0, w = hv.w * w0;
        asm volatile("red.global.add.v4.f32 [%0], {%1,%2,%3,%4};"
                     :: "l"(un + lane), "f"(x), "f"(y), "f"(z), "f"(w)
                     : "memory");
    }
    {
        float4 hv = hs[lane + 32];
        float x = hv.x * w1, y = hv.y * w1, z = hv.z * w1, w = hv.w * w1;
        asm volatile("red.global.add.v4.f32 [%0], {%1,%2,%3,%4};"
                     :: "l"(un + lane + 32), "f"(x), "f"(y), "f"(z), "f"(w)
                     : "memory");
    }
}

// ---------------- Kernel 5: node epilogue (normalize, residuals, conv merge,
//                  BN partial stats); self-clean AFTER the block barrier -----
__global__ void node_final_kernel(const float* __restrict__ gat_bias,
                                  const float* __restrict__ conv_w,
                                  const float* __restrict__ conv_b)
{
    const int d = threadIdx.x;                          // 0..63
    const int n = blockIdx.x * blockDim.y + threadIdx.y;
    __shared__ float shs[8][64];
    __shared__ float shq[8][64];

    float y = 0.f;
    if (n < NN) {
        float acc = conv_b[0];
#pragma unroll
        for (int h = 0; h < NH; h++) {
            float ss = g_ssum[n * NH + h];
            size_t idx = (size_t)n * HO + h * OUT_F + d;
            float un = g_unnorm[idx];
            g_unnorm[idx] = 0.f;  // self-clean (own element, no race)
            float r = un / (ss + 1e-16f) + g_gres[idx] + gat_bias[h * OUT_F + d];
            r = fmaxf(r, 0.f);
            acc += r * conv_w[h];
        }
        y = acc + g_y0[(size_t)n * OUT_F + d];
        g_ybuf[(size_t)n * OUT_F + d] = y;
    }
    shs[threadIdx.y][d] = y;
    shq[threadIdx.y][d] = y * y;
    __syncthreads();   // ALL reads of g_ssum complete before any cleaning below
    if (n < NN && d < NH) {                // self-clean for next launch
        g_ssum[n * NH + d] = 0.f;
        g_mkey[n * NH + d] = 0u;
    }
    if (threadIdx.y == 0) {
        float sv = 0.f, qv = 0.f;
#pragma unroll
        for (int r = 0; r < 8; r++) { sv += shs[r][d]; qv += shq[r][d]; }
        atomicAdd(&g_bnsum[d], sv);
        atomicAdd(&g_bnsq[d],  qv);
    }
}

// ---------------- Kernel 6: BN stats -> scale/shift (+ self-clean) ----------
__global__ void bn_stats_kernel(const float* __restrict__ gamma,
                                const float* __restrict__ beta)
{
    int d = threadIdx.x;
    if (d >= OUT_F) return;
    float mean = g_bnsum[d] / (float)NN;
    float var  = g_bnsq[d] / (float)NN - mean * mean;
    float rstd = rsqrtf(var + BN_EPS);
    float sc = gamma[d] * rstd;
    g_scale[d] = sc;
    g_shift[d] = beta[d] - mean * sc;
    g_bnsum[d] = 0.f;   // self-clean
    g_bnsq[d]  = 0.f;
}

// ---------------- Kernel 7: normalize -> d_out -------------------------------
__global__ void bn_apply_kernel(float* __restrict__ out)
{
    int i = blockIdx.x * blockDim.x + threadIdx.x;
    if (i >= NN * OUT_F) return;
    int d = i & (OUT_F - 1);
    out[i] = g_ybuf[i] * g_scale[d] + g_shift[d];
}

// ---------------- launch -----------------------------------------------------
extern "C" void kernel_launch(void* const* d_in, const int* in_sizes, int n_in,
                              void* d_out, int out_size)
{
    const float* node_feats = (const float*)d_in[0];
    const float* W_fc       = (const float*)d_in[1];
    const float* attn_l     = (const float*)d_in[2];
    const float* attn_r     = (const float*)d_in[3];
    const float* gat_res_w  = (const float*)d_in[4];
    const float* gat_bias   = (const float*)d_in[5];
    const float* conv_w     = (const float*)d_in[6];
    const float* conv_b     = (const float*)d_in[7];
    const float* res_w      = (const float*)d_in[8];
    const float* res_b      = (const float*)d_in[9];
    const float* bn_gamma   = (const float*)d_in[10];
    const float* bn_beta    = (const float*)d_in[11];
    const int*   src        = (const int*)d_in[12];
    const int*   dst        = (const int*)d_in[13];
    float*       out        = (float*)d_out;

    // 1) the three GEMMs
    {
        dim3 grid((NN + 63) / 64, 9);
        gemm_kernel<<<grid, 256>>>(node_feats, W_fc, gat_res_w, res_w, res_b);
    }
    // 2) el / er
    {
        int total = NN * NH;
        elr_kernel<<<(total + 255) / 256, 256>>>(attn_l, attn_r);
    }
    // 3) edge logits + segment max
    edge_max_kernel<<<(EE + 255) / 256, 256>>>(src, dst);
    // 4) exp + segment sum + aggregation (warp per edge)
    {
        long long threads = (long long)EE * 32;
        edge_agg_kernel<<<(int)((threads + 255) / 256), 256>>>(src, dst);
    }
    // 5) node epilogue + BN partials
    {
        dim3 block(64, 8);
        node_final_kernel<<<(NN + 7) / 8, block>>>(gat_bias, conv_w, conv_b);
    }
    // 6) BN stats
    bn_stats_kernel<<<1, 64>>>(bn_gamma, bn_beta);
    // 7) normalize
    bn_apply_kernel<<<(NN * OUT_F + 255) / 256, 256>>>(out);
}

// round 6
// speedup vs baseline: 1.1474x; 1.1450x over previous
#include <cuda_runtime.h>
#include <cuda_bf16.h>
#include <cstdint>

#define NN    50000
#define EE    800000
#define IN_F  128
#define OUT_F 64
#define NH    4
#define HO    256   // NH*OUT_F
#define NEG_SLOPE 0.2f
#define BN_EPS 1e-5f

// ---------------- scratch (device globals; zero-init at load, self-cleaned) --
__device__ float        g_h     [(size_t)NN * HO];     // node_feats @ W_fc
__device__ float        g_gres  [(size_t)NN * HO];     // node_feats @ gat_res_w
__device__ float        g_y0    [(size_t)NN * OUT_F];  // relu(node@res_w + res_b)
__device__ float        g_ybuf  [(size_t)NN * OUT_F];  // pre-BN y
__device__ float        g_el    [NN * NH];
__device__ float        g_er    [NN * NH];
__device__ int          g_deg   [NN];                  // self-cleaned (by scan)
__device__ int          g_off   [NN];                  // csr offsets
__device__ int          g_cursor[NN];                  // self-cleaned (by agg)
__device__ int          g_esrc  [EE];                  // dst-sorted src indices
__device__ float        g_bnsum [OUT_F];               // self-cleaned
__device__ float        g_bnsq  [OUT_F];               // self-cleaned
__device__ float        g_scale [OUT_F];
__device__ float        g_shift [OUT_F];

// ---------------- packed f32x2 FMA (sm_103a FFMA2 — PTX-only) ---------------
__device__ __forceinline__ void ffma2(unsigned long long& c,
                                      unsigned long long a,
                                      unsigned long long b) {
    asm("fma.rn.f32x2 %0, %1, %2, %0;" : "+l"(c) : "l"(a), "l"(b));
}

// ---------------- Kernel 1: three GEMMs in one (col-tile selects weight) ----
// grid.x = ceil(NN/64), grid.y = 9 (0-3 W_fc, 4-7 gat_res_w, 8 res_w), 256 thr
__global__ void gemm_kernel(const float* __restrict__ A,
                            const float* __restrict__ Wfc,
                            const float* __restrict__ Wgres,
                            const float* __restrict__ Wres,
                            const float* __restrict__ res_b)
{
    const int ct = blockIdx.y;
    const float* B;
    int ldb, colbase, mode;
    if (ct < 4)      { B = Wfc;   ldb = HO;    colbase = ct * 64;       mode = 0; }
    else if (ct < 8) { B = Wgres; ldb = HO;    colbase = (ct - 4) * 64; mode = 1; }
    else             { B = Wres;  ldb = OUT_F; colbase = 0;             mode = 2; }

    __shared__ float As [32][68];   // transposed: [k][m]   (272B rows, 16B aligned)
    __shared__ float Bs2[32][132];  // [k][n duplicated x2]  (528B rows, 16B aligned)

    const int row0 = blockIdx.x * 64;
    const int tx = threadIdx.x & 15;
    const int ty = threadIdx.x >> 4;

    // acc[ip][j]: packed rows (ty*4+2ip, ty*4+2ip+1), col tx*4+j
    unsigned long long acc[2][4];
#pragma unroll
    for (int ip = 0; ip < 2; ip++)
#pragma unroll
        for (int j = 0; j < 4; j++) acc[ip][j] = 0ull;

    for (int k0 = 0; k0 < IN_F; k0 += 32) {
        {
            int t = threadIdx.x;
            int r  = t >> 2;          // 0..63
            int kq = (t & 3) * 8;     // 0,8,16,24
            int grow = row0 + r;
            float4 v0, v1;
            if (grow < NN) {
                const float4* ap = reinterpret_cast<const float4*>(A + (size_t)grow * IN_F + k0 + kq);
                v0 = ap[0]; v1 = ap[1];
            } else {
                v0 = make_float4(0.f, 0.f, 0.f, 0.f); v1 = v0;
            }
            As[kq + 0][r] = v0.x; As[kq + 1][r] = v0.y; As[kq + 2][r] = v0.z; As[kq + 3][r] = v0.w;
            As[kq + 4][r] = v1.x; As[kq + 5][r] = v1.y; As[kq + 6][r] = v1.z; As[kq + 7][r] = v1.w;

            // B tile (32 k x 64 cols), store DUPLICATED: {b,b} pairs
            int kr = t >> 3;          // 0..31
            int cq = (t & 7) * 8;     // 0..56
            const float4* bp = reinterpret_cast<const float4*>(B + (size_t)(k0 + kr) * ldb + colbase + cq);
            float4 b0 = bp[0], b1 = bp[1];
            float* dstp = &Bs2[kr][2 * cq];
            *reinterpret_cast<float4*>(dstp +  0) = make_float4(b0.x, b0.x, b0.y, b0.y);
            *reinterpret_cast<float4*>(dstp +  4) = make_float4(b0.z, b0.z, b0.w, b0.w);
            *reinterpret_cast<float4*>(dstp +  8) = make_float4(b1.x, b1.x, b1.y, b1.y);
            *reinterpret_cast<float4*>(dstp + 12) = make_float4(b1.z, b1.z, b1.w, b1.w);
        }
        __syncthreads();

#pragma unroll
        for (int kk = 0; kk < 32; kk++) {
            ulonglong2 ap  = *reinterpret_cast<const ulonglong2*>(&As [kk][ty * 4]);     // {a0,a1},{a2,a3}
            ulonglong2 bp0 = *reinterpret_cast<const ulonglong2*>(&Bs2[kk][tx * 8]);     // {b0,b0},{b1,b1}
            ulonglong2 bp1 = *reinterpret_cast<const ulonglong2*>(&Bs2[kk][tx * 8 + 4]); // {b2,b2},{b3,b3}
            ffma2(acc[0][0], ap.x, bp0.x);
            ffma2(acc[0][1], ap.x, bp0.y);
            ffma2(acc[0][2], ap.x, bp1.x);
            ffma2(acc[0][3], ap.x, bp1.y);
            ffma2(acc[1][0], ap.y, bp0.x);
            ffma2(acc[1][1], ap.y, bp0.y);
            ffma2(acc[1][2], ap.y, bp1.x);
            ffma2(acc[1][3], ap.y, bp1.y);
        }
        __syncthreads();
    }

#pragma unroll
    for (int ip = 0; ip < 2; ip++) {
#pragma unroll
        for (int half = 0; half < 2; half++) {
            int grow = row0 + ty * 4 + 2 * ip + half;
            if (grow >= NN) continue;
#pragma unroll
            for (int j = 0; j < 4; j++) {
                float2 f = *reinterpret_cast<float2*>(&acc[ip][j]);
                float v = half ? f.y : f.x;
                int gcol = colbase + tx * 4 + j;
                if (mode == 0)      g_h   [(size_t)grow * HO + gcol] = v;
                else if (mode == 1) g_gres[(size_t)grow * HO + gcol] = v;
                else                g_y0  [(size_t)grow * OUT_F + gcol] = fmaxf(v + res_b[gcol], 0.f);
            }
        }
    }
}

// ---------------- Kernel 2: el/er per (node, head) ---------------------------
__global__ void elr_kernel(const float* __restrict__ attn_l,
                           const float* __restrict__ attn_r)
{
    int t = blockIdx.x * blockDim.x + threadIdx.x;  // n*4 + h
    if (t >= NN * NH) return;
    int h = t & 3;
    const float4* hp = reinterpret_cast<const float4*>(g_h + (size_t)t * OUT_F);
    const float4* lp = reinterpret_cast<const float4*>(attn_l + h * OUT_F);
    const float4* rp = reinterpret_cast<const float4*>(attn_r + h * OUT_F);
    float el = 0.f, er = 0.f;
#pragma unroll
    for (int j = 0; j < OUT_F / 4; j++) {
        float4 hv = hp[j], lv = lp[j], rv = rp[j];
        el += hv.x * lv.x + hv.y * lv.y + hv.z * lv.z + hv.w * lv.w;
        er += hv.x * rv.x + hv.y * rv.y + hv.z * rv.z + hv.w * rv.w;
    }
    g_el[t] = el;
    g_er[t] = er;
}

// ---------------- Kernel 3a: degree histogram --------------------------------
__global__ void hist_kernel(const int* __restrict__ dst)
{
    int e = blockIdx.x * blockDim.x + threadIdx.x;
    if (e >= EE) return;
    atomicAdd(&g_deg[dst[e]], 1);
}

// ---------------- Kernel 3b: exclusive scan (1 block) + zero g_deg ----------
__global__ void scan_kernel()
{
    const int tid = threadIdx.x;   // 1024 threads
    __shared__ int wsum[32];
    __shared__ int s_carry;
    if (tid == 0) s_carry = 0;
    __syncthreads();
    for (int base = 0; base < NN; base += 1024) {
        int i = base + tid;
        int v = (i < NN) ? g_deg[i] : 0;
        if (i < NN) g_deg[i] = 0;            // self-clean
        int incl = v;
#pragma unroll
        for (int o = 1; o < 32; o <<= 1) {
            int t = __shfl_up_sync(0xffffffffu, incl, o);
            if ((tid & 31) >= o) incl += t;
        }
        if ((tid & 31) == 31) wsum[tid >> 5] = incl;
        __syncthreads();
        if (tid < 32) {
            int w = wsum[tid];
            int wi = w;
#pragma unroll
            for (int o = 1; o < 32; o <<= 1) {
                int t = __shfl_up_sync(0xffffffffu, wi, o);
                if (tid >= o) wi += t;
            }
            wsum[tid] = wi - w;              // exclusive warp offset
        }
        __syncthreads();
        incl += wsum[tid >> 5];
        int carry = s_carry;
        if (i < NN) g_off[i] = carry + incl - v;
        __syncthreads();                      // all reads of s_carry done
        if (tid == 1023) s_carry = carry + incl;
        __syncthreads();
    }
}

// ---------------- Kernel 3c: scatter src into dst-sorted order ---------------
__global__ void scatter_kernel(const int* __restrict__ src,
                               const int* __restrict__ dst)
{
    int e = blockIdx.x * blockDim.x + threadIdx.x;
    if (e >= EE) return;
    int d = dst[e];
    int p = g_off[d] + atomicAdd(&g_cursor[d], 1);
    g_esrc[p] = src[e];
}

// ---------------- Kernel 4: fused per-dst softmax + aggregation + epilogue --
// warp per dst node; 8 warps/block; grid = NN/8 (exact: 50000 = 6250*8)
__global__ void agg_kernel(const float* __restrict__ gat_bias,
                           const float* __restrict__ conv_w,
                           const float* __restrict__ conv_b)
{
    const int lane = threadIdx.x & 31;
    const int w    = threadIdx.x >> 5;      // 0..7
    const int n    = blockIdx.x * 8 + w;

    const int off = g_off[n];
    const int deg = g_cursor[n];

    const float4 er4 = *reinterpret_cast<const float4*>(g_er + n * 4);

    // pass 1: per-head max over incoming edges
    float m0 = -1e30f, m1 = -1e30f, m2 = -1e30f, m3 = -1e30f;
    for (int base = 0; base < deg; base += 32) {
        int e = base + lane;
        int s = (e < deg) ? g_esrc[off + e] : 0;
        float4 elv = *reinterpret_cast<const float4*>(g_el + s * 4);
        float l0 = elv.x + er4.x; l0 = (l0 >= 0.f) ? l0 : NEG_SLOPE * l0;
        float l1 = elv.y + er4.y; l1 = (l1 >= 0.f) ? l1 : NEG_SLOPE * l1;
        float l2 = elv.z + er4.z; l2 = (l2 >= 0.f) ? l2 : NEG_SLOPE * l2;
        float l3 = elv.w + er4.w; l3 = (l3 >= 0.f) ? l3 : NEG_SLOPE * l3;
        if (e < deg) {
            m0 = fmaxf(m0, l0); m1 = fmaxf(m1, l1);
            m2 = fmaxf(m2, l2); m3 = fmaxf(m3, l3);
        }
    }
#pragma unroll
    for (int o = 16; o; o >>= 1) {
        m0 = fmaxf(m0, __shfl_xor_sync(0xffffffffu, m0, o));
        m1 = fmaxf(m1, __shfl_xor_sync(0xffffffffu, m1, o));
        m2 = fmaxf(m2, __shfl_xor_sync(0xffffffffu, m2, o));
        m3 = fmaxf(m3, __shfl_xor_sync(0xffffffffu, m3, o));
    }

    // pass 2: exp, segment sum, weighted aggregation (in registers)
    float s0 = 0.f, s1 = 0.f, s2 = 0.f, s3 = 0.f;
    float4 acc0 = make_float4(0.f, 0.f, 0.f, 0.f);
    float4 acc1 = make_float4(0.f, 0.f, 0.f, 0.f);
    for (int base = 0; base < deg; base += 32) {
        int cnt = min(32, deg - base);
        int e = base + lane;
        int sidx = (e < deg) ? g_esrc[off + e] : 0;
        float4 elv = *reinterpret_cast<const float4*>(g_el + sidx * 4);
        float l0 = elv.x + er4.x; l0 = (l0 >= 0.f) ? l0 : NEG_SLOPE * l0;
        float l1 = elv.y + er4.y; l1 = (l1 >= 0.f) ? l1 : NEG_SLOPE * l1;
        float l2 = elv.z + er4.z; l2 = (l2 >= 0.f) ? l2 : NEG_SLOPE * l2;
        float l3 = elv.w + er4.w; l3 = (l3 >= 0.f) ? l3 : NEG_SLOPE * l3;
        float a0 = (e < deg) ? __expf(l0 - m0) : 0.f;
        float a1 = (e < deg) ? __expf(l1 - m1) : 0.f;
        float a2 = (e < deg) ? __expf(l2 - m2) : 0.f;
        float a3 = (e < deg) ? __expf(l3 - m3) : 0.f;
        s0 += a0; s1 += a1; s2 += a2; s3 += a3;

        for (int ee = 0; ee < cnt; ee++) {
            int   sv = __shfl_sync(0xffffffffu, sidx, ee);
            float b0 = __shfl_sync(0xffffffffu, a0, ee);
            float b1 = __shfl_sync(0xffffffffu, a1, ee);
            float b2 = __shfl_sync(0xffffffffu, a2, ee);
            float b3 = __shfl_sync(0xffffffffu, a3, ee);
            float w0 = (lane < 16) ? b0 : b1;
            float w1 = (lane < 16) ? b2 : b3;
            const float4* hrow = reinterpret_cast<const float4*>(g_h + (size_t)sv * HO);
            float4 h0 = hrow[lane];
            float4 h1 = hrow[lane + 32];
            acc0.x = fmaf(w0, h0.x, acc0.x); acc0.y = fmaf(w0, h0.y, acc0.y);
            acc0.z = fmaf(w0, h0.z, acc0.z); acc0.w = fmaf(w0, h0.w, acc0.w);
            acc1.x = fmaf(w1, h1.x, acc1.x); acc1.y = fmaf(w1, h1.y, acc1.y);
            acc1.z = fmaf(w1, h1.z, acc1.z); acc1.w = fmaf(w1, h1.w, acc1.w);
        }
    }
#pragma unroll
    for (int o = 16; o; o >>= 1) {
        s0 += __shfl_xor_sync(0xffffffffu, s0, o);
        s1 += __shfl_xor_sync(0xffffffffu, s1, o);
        s2 += __shfl_xor_sync(0xffffffffu, s2, o);
        s3 += __shfl_xor_sync(0xffffffffu, s3, o);
    }

    // normalize + gat residual + bias + relu + conv head-merge
    // lane l holds cols c4..c4+3 for heads hA (acc0) and hB (acc1)
    const float invA = 1.f / (((lane < 16) ? s0 : s1) + 1e-16f);
    const float invB = 1.f / (((lane < 16) ? s2 : s3) + 1e-16f);
    const int hA = (lane < 16) ? 0 : 1;
    const int hB = (lane < 16) ? 2 : 3;
    const int c4 = (lane & 15) * 4;
    const float4 gA = *reinterpret_cast<const float4*>(g_gres + (size_t)n * HO + hA * OUT_F + c4);
    const float4 gB = *reinterpret_cast<const float4*>(g_gres + (size_t)n * HO + hB * OUT_F + c4);
    const float4 bA = *reinterpret_cast<const float4*>(gat_bias + hA * OUT_F + c4);
    const float4 bB = *reinterpret_cast<const float4*>(gat_bias + hB * OUT_F + c4);
    const float cwA = conv_w[hA], cwB = conv_w[hB];

    float4 part;
    part.x = fmaxf(acc0.x * invA + gA.x + bA.x, 0.f) * cwA + fmaxf(acc1.x * invB + gB.x + bB.x, 0.f) * cwB;
    part.y = fmaxf(acc0.y * invA + gA.y + bA.y, 0.f) * cwA + fmaxf(acc1.y * invB + gB.y + bB.y, 0.f) * cwB;
    part.z = fmaxf(acc0.z * invA + gA.z + bA.z, 0.f) * cwA + fmaxf(acc1.z * invB + gB.z + bB.z, 0.f) * cwB;
    part.w = fmaxf(acc0.w * invA + gA.w + bA.w, 0.f) * cwA + fmaxf(acc1.w * invB + gB.w + bB.w, 0.f) * cwB;
    part.x += __shfl_xor_sync(0xffffffffu, part.x, 16);
    part.y += __shfl_xor_sync(0xffffffffu, part.y, 16);
    part.z += __shfl_xor_sync(0xffffffffu, part.z, 16);
    part.w += __shfl_xor_sync(0xffffffffu, part.w, 16);

    __shared__ float shs[8][68];
    __shared__ float shq[8][68];
    if (lane < 16) {
        const float4 y0v = *reinterpret_cast<const float4*>(g_y0 + (size_t)n * OUT_F + c4);
        const float cb = conv_b[0];
        float4 y4;
        y4.x = part.x + cb + y0v.x;
        y4.y = part.y + cb + y0v.y;
        y4.z = part.z + cb + y0v.z;
        y4.w = part.w + cb + y0v.w;
        *reinterpret_cast<float4*>(g_ybuf + (size_t)n * OUT_F + c4) = y4;
        *reinterpret_cast<float4*>(&shs[w][c4]) = y4;
        float4 q = make_float4(y4.x * y4.x, y4.y * y4.y, y4.z * y4.z, y4.w * y4.w);
        *reinterpret_cast<float4*>(&shq[w][c4]) = q;
    }
    if (lane == 0) g_cursor[n] = 0;          // self-clean for next launch
    __syncthreads();

    const int t = threadIdx.x;
    if (t < 64) {
        float sv = 0.f;
#pragma unroll
        for (int r = 0; r < 8; r++) sv += shs[r][t];
        atomicAdd(&g_bnsum[t], sv);
    } else if (t >= 128 && t < 192) {
        int d = t - 128;
        float qv = 0.f;
#pragma unroll
        for (int r = 0; r < 8; r++) qv += shq[r][d];
        atomicAdd(&g_bnsq[d], qv);
    }
}

// ---------------- Kernel 5: BN stats -> scale/shift (+ self-clean) ----------
__global__ void bn_stats_kernel(const float* __restrict__ gamma,
                                const float* __restrict__ beta)
{
    int d = threadIdx.x;
    if (d >= OUT_F) return;
    float mean = g_bnsum[d] / (float)NN;
    float var  = g_bnsq[d] / (float)NN - mean * mean;
    float rstd = rsqrtf(var + BN_EPS);
    float sc = gamma[d] * rstd;
    g_scale[d] = sc;
    g_shift[d] = beta[d] - mean * sc;
    g_bnsum[d] = 0.f;   // self-clean
    g_bnsq[d]  = 0.f;
}

// ---------------- Kernel 6: normalize -> d_out -------------------------------
__global__ void bn_apply_kernel(float* __restrict__ out)
{
    int i = blockIdx.x * blockDim.x + threadIdx.x;
    if (i >= NN * OUT_F) return;
    int d = i & (OUT_F - 1);
    out[i] = g_ybuf[i] * g_scale[d] + g_shift[d];
}

// ---------------- launch -----------------------------------------------------
extern "C" void kernel_launch(void* const* d_in, const int* in_sizes, int n_in,
                              void* d_out, int out_size)
{
    const float* node_feats = (const float*)d_in[0];
    const float* W_fc       = (const float*)d_in[1];
    const float* attn_l     = (const float*)d_in[2];
    const float* attn_r     = (const float*)d_in[3];
    const float* gat_res_w  = (const float*)d_in[4];
    const float* gat_bias   = (const float*)d_in[5];
    const float* conv_w     = (const float*)d_in[6];
    const float* conv_b     = (const float*)d_in[7];
    const float* res_w      = (const float*)d_in[8];
    const float* res_b      = (const float*)d_in[9];
    const float* bn_gamma   = (const float*)d_in[10];
    const float* bn_beta    = (const float*)d_in[11];
    const int*   src        = (const int*)d_in[12];
    const int*   dst        = (const int*)d_in[13];
    float*       out        = (float*)d_out;

    // edge sort (independent of GEMM output)
    hist_kernel<<<(EE + 255) / 256, 256>>>(dst);
    scan_kernel<<<1, 1024>>>();
    scatter_kernel<<<(EE + 255) / 256, 256>>>(src, dst);

    // three GEMMs
    {
        dim3 grid((NN + 63) / 64, 9);
        gemm_kernel<<<grid, 256>>>(node_feats, W_fc, gat_res_w, res_w, res_b);
    }
    // el / er
    elr_kernel<<<(NN * NH + 255) / 256, 256>>>(attn_l, attn_r);
    // fused softmax + aggregation + node epilogue + BN partials
    agg_kernel<<<NN / 8, 256>>>(gat_bias, conv_w, conv_b);
    // BN stats
    bn_stats_kernel<<<1, 64>>>(bn_gamma, bn_beta);
    // normalize
    bn_apply_kernel<<<(NN * OUT_F + 255) / 256, 256>>>(out);
}

// round 7
// speedup vs baseline: 2.2058x; 1.9224x over previous
#include <cuda_runtime.h>
#include <cuda_bf16.h>
#include <cstdint>

#define NN    50000
#define EE    800000
#define IN_F  128
#define OUT_F 64
#define NH    4
#define HO    256   // NH*OUT_F
#define NEG_SLOPE 0.2f
#define BN_EPS 1e-5f

#define BM 128
#define BNT 128
#define BK 16

// ---------------- scratch (device globals; zero-init at load, self-cleaned) --
__device__ float        g_h     [(size_t)NN * HO];     // node_feats @ W_fc
__device__ float        g_gres  [(size_t)NN * HO];     // node_feats @ gat_res_w
__device__ float        g_y0    [(size_t)NN * OUT_F];  // relu(node@res_w + res_b)
__device__ float        g_ybuf  [(size_t)NN * OUT_F];  // pre-BN y
__device__ float        g_el    [NN * NH];
__device__ float        g_er    [NN * NH];
__device__ int          g_deg   [NN];                  // self-cleaned (by scan)
__device__ int          g_off   [NN];                  // csr offsets
__device__ int          g_cursor[NN];                  // self-cleaned (by agg)
__device__ int          g_esrc  [EE];                  // dst-sorted src indices
__device__ float        g_bnsum [OUT_F];               // self-cleaned
__device__ float        g_bnsq  [OUT_F];               // self-cleaned
__device__ float        g_scale [OUT_F];
__device__ float        g_shift [OUT_F];

// ---------------- packed f32x2 helpers (sm_103a FFMA2 — PTX-only) -----------
__device__ __forceinline__ void ffma2(unsigned long long& c,
                                      unsigned long long a,
                                      unsigned long long b) {
    asm("fma.rn.f32x2 %0, %1, %2, %0;" : "+l"(c) : "l"(a), "l"(b));
}
__device__ __forceinline__ unsigned long long pack2(float x) {
    unsigned long long r;
    asm("mov.b64 %0, {%1, %1};" : "=l"(r) : "f"(x));
    return r;
}

// ---------------- Kernel 1: three GEMMs in one + fused el/er epilogue -------
// grid.x = ceil(NN/128)=391, grid.y = 5:
//   ct 0: Wfc cols 0-127 (heads 0,1)   ct 1: Wfc cols 128-255 (heads 2,3)
//   ct 2: gres cols 0-127              ct 3: gres cols 128-255
//   ct 4: res  cols 0-63
// 256 threads, 8x8 microtile (rows packed in f32x2 pairs)
__global__ void __launch_bounds__(256, 2)
gemm_kernel(const float* __restrict__ A,
            const float* __restrict__ Wfc,
            const float* __restrict__ Wgres,
            const float* __restrict__ Wres,
            const float* __restrict__ res_b,
            const float* __restrict__ attn_l,
            const float* __restrict__ attn_r)
{
    const int ct = blockIdx.y;
    const float* B;
    int ldb, colbase, mode;
    if (ct < 2)      { B = Wfc;   ldb = HO;    colbase = ct * 128;       mode = 0; }
    else if (ct < 4) { B = Wgres; ldb = HO;    colbase = (ct - 2) * 128; mode = 1; }
    else             { B = Wres;  ldb = OUT_F; colbase = 0;              mode = 2; }

    __shared__ float As[BK][BM + 8];    // k-major: [k][m], 544B rows (16B aligned)
    __shared__ float Bs[BK][BNT + 4];   // [k][n],          528B rows (16B aligned)

    const int t    = threadIdx.x;
    const int tx   = t & 15;
    const int ty   = t >> 4;
    const int row0 = blockIdx.x * BM;

    // A load mapping: r = t&127 (row), kq = (t>>7)*8 (k-offset 0 or 8)
    const int ar  = t & 127;
    const int akq = (t >> 7) * 8;
    // B load mapping: kr = t>>4 (k 0..15), cq = (t&15)*8
    const int bkr = t >> 4;
    const int bcq = (t & 15) * 8;
    const bool bvalid = (mode != 2) || (bcq < OUT_F);

    unsigned long long acc[4][8];       // acc[ip][j]: rows (8ty+2ip, 8ty+2ip+1), col tx*8+j
#pragma unroll
    for (int ip = 0; ip < 4; ip++)
#pragma unroll
        for (int j = 0; j < 8; j++) acc[ip][j] = 0ull;

    float4 av0, av1, bv0, bv1;
    // prefetch tile 0
    {
        int grow = row0 + ar;
        if (grow < NN) {
            const float4* ap = reinterpret_cast<const float4*>(A + (size_t)grow * IN_F + akq);
            av0 = ap[0]; av1 = ap[1];
        } else { av0 = make_float4(0.f,0.f,0.f,0.f); av1 = av0; }
        if (bvalid) {
            const float4* bp = reinterpret_cast<const float4*>(B + (size_t)bkr * ldb + colbase + bcq);
            bv0 = bp[0]; bv1 = bp[1];
        } else { bv0 = make_float4(0.f,0.f,0.f,0.f); bv1 = bv0; }
    }

    for (int kt = 0; kt < IN_F / BK; kt++) {
        // store current tile regs -> smem
        As[akq + 0][ar] = av0.x; As[akq + 1][ar] = av0.y;
        As[akq + 2][ar] = av0.z; As[akq + 3][ar] = av0.w;
        As[akq + 4][ar] = av1.x; As[akq + 5][ar] = av1.y;
        As[akq + 6][ar] = av1.z; As[akq + 7][ar] = av1.w;
        *reinterpret_cast<float4*>(&Bs[bkr][bcq])     = bv0;
        *reinterpret_cast<float4*>(&Bs[bkr][bcq + 4]) = bv1;
        __syncthreads();

        // prefetch next tile (latency hidden behind the kk loop)
        if (kt + 1 < IN_F / BK) {
            int k0 = (kt + 1) * BK;
            int grow = row0 + ar;
            if (grow < NN) {
                const float4* ap = reinterpret_cast<const float4*>(A + (size_t)grow * IN_F + k0 + akq);
                av0 = ap[0]; av1 = ap[1];
            } else { av0 = make_float4(0.f,0.f,0.f,0.f); av1 = av0; }
            if (bvalid) {
                const float4* bp = reinterpret_cast<const float4*>(B + (size_t)(k0 + bkr) * ldb + colbase + bcq);
                bv0 = bp[0]; bv1 = bp[1];
            }
        }

#pragma unroll
        for (int kk = 0; kk < BK; kk++) {
            ulonglong2 ap0 = *reinterpret_cast<const ulonglong2*>(&As[kk][ty * 8]);      // {a0,a1},{a2,a3}
            ulonglong2 ap1 = *reinterpret_cast<const ulonglong2*>(&As[kk][ty * 8 + 4]);  // {a4,a5},{a6,a7}
            float4 b0 = *reinterpret_cast<const float4*>(&Bs[kk][tx * 8]);
            float4 b1 = *reinterpret_cast<const float4*>(&Bs[kk][tx * 8 + 4]);
            unsigned long long bp[8];
            bp[0] = pack2(b0.x); bp[1] = pack2(b0.y); bp[2] = pack2(b0.z); bp[3] = pack2(b0.w);
            bp[4] = pack2(b1.x); bp[5] = pack2(b1.y); bp[6] = pack2(b1.z); bp[7] = pack2(b1.w);
#pragma unroll
            for (int j = 0; j < 8; j++) {
                ffma2(acc[0][j], ap0.x, bp[j]);
                ffma2(acc[1][j], ap0.y, bp[j]);
                ffma2(acc[2][j], ap1.x, bp[j]);
                ffma2(acc[3][j], ap1.y, bp[j]);
            }
        }
        __syncthreads();
    }

    // ---------------- store outputs ----------------
#pragma unroll
    for (int ip = 0; ip < 4; ip++) {
#pragma unroll
        for (int half = 0; half < 2; half++) {
            int grow = row0 + ty * 8 + 2 * ip + half;
            if (grow >= NN) continue;
            // assemble two float4 (cols j 0-3 and 4-7)
            float4 v0, v1;
            {
                float2 f0 = *reinterpret_cast<float2*>(&acc[ip][0]);
                float2 f1 = *reinterpret_cast<float2*>(&acc[ip][1]);
                float2 f2 = *reinterpret_cast<float2*>(&acc[ip][2]);
                float2 f3 = *reinterpret_cast<float2*>(&acc[ip][3]);
                float2 f4 = *reinterpret_cast<float2*>(&acc[ip][4]);
                float2 f5 = *reinterpret_cast<float2*>(&acc[ip][5]);
                float2 f6 = *reinterpret_cast<float2*>(&acc[ip][6]);
                float2 f7 = *reinterpret_cast<float2*>(&acc[ip][7]);
                if (half == 0) { v0 = make_float4(f0.x,f1.x,f2.x,f3.x); v1 = make_float4(f4.x,f5.x,f6.x,f7.x); }
                else           { v0 = make_float4(f0.y,f1.y,f2.y,f3.y); v1 = make_float4(f4.y,f5.y,f6.y,f7.y); }
            }
            int gcol = colbase + tx * 8;
            if (mode == 0) {
                *reinterpret_cast<float4*>(g_h + (size_t)grow * HO + gcol)     = v0;
                *reinterpret_cast<float4*>(g_h + (size_t)grow * HO + gcol + 4) = v1;
            } else if (mode == 1) {
                *reinterpret_cast<float4*>(g_gres + (size_t)grow * HO + gcol)     = v0;
                *reinterpret_cast<float4*>(g_gres + (size_t)grow * HO + gcol + 4) = v1;
            } else if (tx < 8) {
                const float4 rb0 = *reinterpret_cast<const float4*>(res_b + gcol);
                const float4 rb1 = *reinterpret_cast<const float4*>(res_b + gcol + 4);
                v0.x = fmaxf(v0.x + rb0.x, 0.f); v0.y = fmaxf(v0.y + rb0.y, 0.f);
                v0.z = fmaxf(v0.z + rb0.z, 0.f); v0.w = fmaxf(v0.w + rb0.w, 0.f);
                v1.x = fmaxf(v1.x + rb1.x, 0.f); v1.y = fmaxf(v1.y + rb1.y, 0.f);
                v1.z = fmaxf(v1.z + rb1.z, 0.f); v1.w = fmaxf(v1.w + rb1.w, 0.f);
                *reinterpret_cast<float4*>(g_y0 + (size_t)grow * OUT_F + gcol)     = v0;
                *reinterpret_cast<float4*>(g_y0 + (size_t)grow * OUT_F + gcol + 4) = v1;
            }
        }
    }

    // ---------------- fused el/er epilogue (mode 0 only) ----------------
    if (mode == 0) {
        const int head = ct * 2 + (tx >> 3);        // this thread's 8 cols lie in ONE head
        const int hc   = (tx & 7) * 8;              // head-local col base
        float al[8], arr[8];
        {
            float4 a0 = *reinterpret_cast<const float4*>(attn_l + head * OUT_F + hc);
            float4 a1 = *reinterpret_cast<const float4*>(attn_l + head * OUT_F + hc + 4);
            al[0]=a0.x; al[1]=a0.y; al[2]=a0.z; al[3]=a0.w; al[4]=a1.x; al[5]=a1.y; al[6]=a1.z; al[7]=a1.w;
            float4 r0 = *reinterpret_cast<const float4*>(attn_r + head * OUT_F + hc);
            float4 r1 = *reinterpret_cast<const float4*>(attn_r + head * OUT_F + hc + 4);
            arr[0]=r0.x; arr[1]=r0.y; arr[2]=r0.z; arr[3]=r0.w; arr[4]=r1.x; arr[5]=r1.y; arr[6]=r1.z; arr[7]=r1.w;
        }
#pragma unroll
        for (int ip = 0; ip < 4; ip++) {
            float el_lo = 0.f, el_hi = 0.f, er_lo = 0.f, er_hi = 0.f;
#pragma unroll
            for (int j = 0; j < 8; j++) {
                float2 h2 = *reinterpret_cast<float2*>(&acc[ip][j]);
                el_lo = fmaf(h2.x, al[j],  el_lo);
                el_hi = fmaf(h2.y, al[j],  el_hi);
                er_lo = fmaf(h2.x, arr[j], er_lo);
                er_hi = fmaf(h2.y, arr[j], er_hi);
            }
#pragma unroll
            for (int d = 1; d < 8; d <<= 1) {       // reduce over tx&7 (lane bits 0-2)
                el_lo += __shfl_xor_sync(0xffffffffu, el_lo, d);
                el_hi += __shfl_xor_sync(0xffffffffu, el_hi, d);
                er_lo += __shfl_xor_sync(0xffffffffu, er_lo, d);
                er_hi += __shfl_xor_sync(0xffffffffu, er_hi, d);
            }
            if ((tx & 7) == 0) {
                int r0g = row0 + ty * 8 + 2 * ip;
                if (r0g < NN)     { g_el[r0g * NH + head] = el_lo; g_er[r0g * NH + head] = er_lo; }
                if (r0g + 1 < NN) { g_el[(r0g + 1) * NH + head] = el_hi; g_er[(r0g + 1) * NH + head] = er_hi; }
            }
        }
    }
}

// ---------------- Kernel 3a: degree histogram --------------------------------
__global__ void hist_kernel(const int* __restrict__ dst)
{
    int e = blockIdx.x * blockDim.x + threadIdx.x;
    if (e >= EE) return;
    atomicAdd(&g_deg[dst[e]], 1);
}

// ---------------- Kernel 3b: exclusive scan (1 block) + zero g_deg ----------
__global__ void scan_kernel()
{
    const int tid = threadIdx.x;   // 1024 threads
    __shared__ int wsum[32];
    __shared__ int s_carry;
    if (tid == 0) s_carry = 0;
    __syncthreads();
    for (int base = 0; base < NN; base += 1024) {
        int i = base + tid;
        int v = (i < NN) ? g_deg[i] : 0;
        if (i < NN) g_deg[i] = 0;            // self-clean
        int incl = v;
#pragma unroll
        for (int o = 1; o < 32; o <<= 1) {
            int t = __shfl_up_sync(0xffffffffu, incl, o);
            if ((tid & 31) >= o) incl += t;
        }
        if ((tid & 31) == 31) wsum[tid >> 5] = incl;
        __syncthreads();
        if (tid < 32) {
            int w = wsum[tid];
            int wi = w;
#pragma unroll
            for (int o = 1; o < 32; o <<= 1) {
                int t = __shfl_up_sync(0xffffffffu, wi, o);
                if (tid >= o) wi += t;
            }
            wsum[tid] = wi - w;              // exclusive warp offset
        }
        __syncthreads();
        incl += wsum[tid >> 5];
        int carry = s_carry;
        if (i < NN) g_off[i] = carry + incl - v;
        __syncthreads();                      // all reads of s_carry done
        if (tid == 1023) s_carry = carry + incl;
        __syncthreads();
    }
}

// ---------------- Kernel 3c: scatter src into dst-sorted order ---------------
__global__ void scatter_kernel(const int* __restrict__ src,
                               const int* __restrict__ dst)
{
    int e = blockIdx.x * blockDim.x + threadIdx.x;
    if (e >= EE) return;
    int d = dst[e];
    int p = g_off[d] + atomicAdd(&g_cursor[d], 1);
    g_esrc[p] = src[e];
}

// ---------------- Kernel 4: fused per-dst softmax + aggregation + epilogue --
// warp per dst node; 8 warps/block; grid = NN/8 (exact: 50000 = 6250*8)
__global__ void agg_kernel(const float* __restrict__ gat_bias,
                           const float* __restrict__ conv_w,
                           const float* __restrict__ conv_b)
{
    const int lane = threadIdx.x & 31;
    const int w    = threadIdx.x >> 5;      // 0..7
    const int n    = blockIdx.x * 8 + w;

    const int off = g_off[n];
    const int deg = g_cursor[n];

    const float4 er4 = *reinterpret_cast<const float4*>(g_er + n * 4);

    // pass 1: per-head max over incoming edges
    float m0 = -1e30f, m1 = -1e30f, m2 = -1e30f, m3 = -1e30f;
    for (int base = 0; base < deg; base += 32) {
        int e = base + lane;
        int s = (e < deg) ? g_esrc[off + e] : 0;
        float4 elv = *reinterpret_cast<const float4*>(g_el + s * 4);
        float l0 = elv.x + er4.x; l0 = (l0 >= 0.f) ? l0 : NEG_SLOPE * l0;
        float l1 = elv.y + er4.y; l1 = (l1 >= 0.f) ? l1 : NEG_SLOPE * l1;
        float l2 = elv.z + er4.z; l2 = (l2 >= 0.f) ? l2 : NEG_SLOPE * l2;
        float l3 = elv.w + er4.w; l3 = (l3 >= 0.f) ? l3 : NEG_SLOPE * l3;
        if (e < deg) {
            m0 = fmaxf(m0, l0); m1 = fmaxf(m1, l1);
            m2 = fmaxf(m2, l2); m3 = fmaxf(m3, l3);
        }
    }
#pragma unroll
    for (int o = 16; o; o >>= 1) {
        m0 = fmaxf(m0, __shfl_xor_sync(0xffffffffu, m0, o));
        m1 = fmaxf(m1, __shfl_xor_sync(0xffffffffu, m1, o));
        m2 = fmaxf(m2, __shfl_xor_sync(0xffffffffu, m2, o));
        m3 = fmaxf(m3, __shfl_xor_sync(0xffffffffu, m3, o));
    }

    // pass 2: exp, segment sum, weighted aggregation (in registers)
    float s0 = 0.f, s1 = 0.f, s2 = 0.f, s3 = 0.f;
    float4 acc0 = make_float4(0.f, 0.f, 0.f, 0.f);
    float4 acc1 = make_float4(0.f, 0.f, 0.f, 0.f);
    for (int base = 0; base < deg; base += 32) {
        int cnt = min(32, deg - base);
        int e = base + lane;
        int sidx = (e < deg) ? g_esrc[off + e] : 0;
        float4 elv = *reinterpret_cast<const float4*>(g_el + sidx * 4);
        float l0 = elv.x + er4.x; l0 = (l0 >= 0.f) ? l0 : NEG_SLOPE * l0;
        float l1 = elv.y + er4.y; l1 = (l1 >= 0.f) ? l1 : NEG_SLOPE * l1;
        float l2 = elv.z + er4.z; l2 = (l2 >= 0.f) ? l2 : NEG_SLOPE * l2;
        float l3 = elv.w + er4.w; l3 = (l3 >= 0.f) ? l3 : NEG_SLOPE * l3;
        float a0 = (e < deg) ? __expf(l0 - m0) : 0.f;
        float a1 = (e < deg) ? __expf(l1 - m1) : 0.f;
        float a2 = (e < deg) ? __expf(l2 - m2) : 0.f;
        float a3 = (e < deg) ? __expf(l3 - m3) : 0.f;
        s0 += a0; s1 += a1; s2 += a2; s3 += a3;

        for (int ee = 0; ee < cnt; ee++) {
            int   sv = __shfl_sync(0xffffffffu, sidx, ee);
            float b0 = __shfl_sync(0xffffffffu, a0, ee);
            float b1 = __shfl_sync(0xffffffffu, a1, ee);
            float b2 = __shfl_sync(0xffffffffu, a2, ee);
            float b3 = __shfl_sync(0xffffffffu, a3, ee);
            float w0 = (lane < 16) ? b0 : b1;
            float w1 = (lane < 16) ? b2 : b3;
            const float4* hrow = reinterpret_cast<const float4*>(g_h + (size_t)sv * HO);
            float4 h0 = hrow[lane];
            float4 h1 = hrow[lane + 32];
            acc0.x = fmaf(w0, h0.x, acc0.x); acc0.y = fmaf(w0, h0.y, acc0.y);
            acc0.z = fmaf(w0, h0.z, acc0.z); acc0.w = fmaf(w0, h0.w, acc0.w);
            acc1.x = fmaf(w1, h1.x, acc1.x); acc1.y = fmaf(w1, h1.y, acc1.y);
            acc1.z = fmaf(w1, h1.z, acc1.z); acc1.w = fmaf(w1, h1.w, acc1.w);
        }
    }
#pragma unroll
    for (int o = 16; o; o >>= 1) {
        s0 += __shfl_xor_sync(0xffffffffu, s0, o);
        s1 += __shfl_xor_sync(0xffffffffu, s1, o);
        s2 += __shfl_xor_sync(0xffffffffu, s2, o);
        s3 += __shfl_xor_sync(0xffffffffu, s3, o);
    }

    // normalize + gat residual + bias + relu + conv head-merge
    const float invA = 1.f / (((lane < 16) ? s0 : s1) + 1e-16f);
    const float invB = 1.f / (((lane < 16) ? s2 : s3) + 1e-16f);
    const int hA = (lane < 16) ? 0 : 1;
    const int hB = (lane < 16) ? 2 : 3;
    const int c4 = (lane & 15) * 4;
    const float4 gA = *reinterpret_cast<const float4*>(g_gres + (size_t)n * HO + hA * OUT_F + c4);
    const float4 gB = *reinterpret_cast<const float4*>(g_gres + (size_t)n * HO + hB * OUT_F + c4);
    const float4 bA = *reinterpret_cast<const float4*>(gat_bias + hA * OUT_F + c4);
    const float4 bB = *reinterpret_cast<const float4*>(gat_bias + hB * OUT_F + c4);
    const float cwA = conv_w[hA], cwB = conv_w[hB];

    float4 part;
    part.x = fmaxf(acc0.x * invA + gA.x + bA.x, 0.f) * cwA + fmaxf(acc1.x * invB + gB.x + bB.x, 0.f) * cwB;
    part.y = fmaxf(acc0.y * invA + gA.y + bA.y, 0.f) * cwA + fmaxf(acc1.y * invB + gB.y + bB.y, 0.f) * cwB;
    part.z = fmaxf(acc0.z * invA + gA.z + bA.z, 0.f) * cwA + fmaxf(acc1.z * invB + gB.z + bB.z, 0.f) * cwB;
    part.w = fmaxf(acc0.w * invA + gA.w + bA.w, 0.f) * cwA + fmaxf(acc1.w * invB + gB.w + bB.w, 0.f) * cwB;
    part.x += __shfl_xor_sync(0xffffffffu, part.x, 16);
    part.y += __shfl_xor_sync(0xffffffffu, part.y, 16);
    part.z += __shfl_xor_sync(0xffffffffu, part.z, 16);
    part.w += __shfl_xor_sync(0xffffffffu, part.w, 16);

    __shared__ float shs[8][68];
    __shared__ float shq[8][68];
    if (lane < 16) {
        const float4 y0v = *reinterpret_cast<const float4*>(g_y0 + (size_t)n * OUT_F + c4);
        const float cb = conv_b[0];
        float4 y4;
        y4.x = part.x + cb + y0v.x;
        y4.y = part.y + cb + y0v.y;
        y4.z = part.z + cb + y0v.z;
        y4.w = part.w + cb + y0v.w;
        *reinterpret_cast<float4*>(g_ybuf + (size_t)n * OUT_F + c4) = y4;
        *reinterpret_cast<float4*>(&shs[w][c4]) = y4;
        float4 q = make_float4(y4.x * y4.x, y4.y * y4.y, y4.z * y4.z, y4.w * y4.w);
        *reinterpret_cast<float4*>(&shq[w][c4]) = q;
    }
    if (lane == 0) g_cursor[n] = 0;          // self-clean for next launch
    __syncthreads();

    const int t = threadIdx.x;
    if (t < 64) {
        float sv = 0.f;
#pragma unroll
        for (int r = 0; r < 8; r++) sv += shs[r][t];
        atomicAdd(&g_bnsum[t], sv);
    } else if (t >= 128 && t < 192) {
        int d = t - 128;
        float qv = 0.f;
#pragma unroll
        for (int r = 0; r < 8; r++) qv += shq[r][d];
        atomicAdd(&g_bnsq[d], qv);
    }
}

// ---------------- Kernel 5: BN stats -> scale/shift (+ self-clean) ----------
__global__ void bn_stats_kernel(const float* __restrict__ gamma,
                                const float* __restrict__ beta)
{
    int d = threadIdx.x;
    if (d >= OUT_F) return;
    float mean = g_bnsum[d] / (float)NN;
    float var  = g_bnsq[d] / (float)NN - mean * mean;
    float rstd = rsqrtf(var + BN_EPS);
    float sc = gamma[d] * rstd;
    g_scale[d] = sc;
    g_shift[d] = beta[d] - mean * sc;
    g_bnsum[d] = 0.f;   // self-clean
    g_bnsq[d]  = 0.f;
}

// ---------------- Kernel 6: normalize -> d_out -------------------------------
__global__ void bn_apply_kernel(float* __restrict__ out)
{
    int i = blockIdx.x * blockDim.x + threadIdx.x;
    if (i >= NN * OUT_F) return;
    int d = i & (OUT_F - 1);
    out[i] = g_ybuf[i] * g_scale[d] + g_shift[d];
}

// ---------------- launch -----------------------------------------------------
extern "C" void kernel_launch(void* const* d_in, const int* in_sizes, int n_in,
                              void* d_out, int out_size)
{
    const float* node_feats = (const float*)d_in[0];
    const float* W_fc       = (const float*)d_in[1];
    const float* attn_l     = (const float*)d_in[2];
    const float* attn_r     = (const float*)d_in[3];
    const float* gat_res_w  = (const float*)d_in[4];
    const float* gat_bias   = (const float*)d_in[5];
    const float* conv_w     = (const float*)d_in[6];
    const float* conv_b     = (const float*)d_in[7];
    const float* res_w      = (const float*)d_in[8];
    const float* res_b      = (const float*)d_in[9];
    const float* bn_gamma   = (const float*)d_in[10];
    const float* bn_beta    = (const float*)d_in[11];
    const int*   src        = (const int*)d_in[12];
    const int*   dst        = (const int*)d_in[13];
    float*       out        = (float*)d_out;

    // edge sort (independent of GEMM output)
    hist_kernel<<<(EE + 255) / 256, 256>>>(dst);
    scan_kernel<<<1, 1024>>>();
    scatter_kernel<<<(EE + 255) / 256, 256>>>(src, dst);

    // three GEMMs (+ fused el/er epilogue)
    {
        dim3 grid((NN + BM - 1) / BM, 5);
        gemm_kernel<<<grid, 256>>>(node_feats, W_fc, gat_res_w, res_w, res_b,
                                   attn_l, attn_r);
    }
    // fused softmax + aggregation + node epilogue + BN partials
    agg_kernel<<<NN / 8, 256>>>(gat_bias, conv_w, conv_b);
    // BN stats
    bn_stats_kernel<<<1, 64>>>(bn_gamma, bn_beta);
    // normalize
    bn_apply_kernel<<<(NN * OUT_F + 255) / 256, 256>>>(out);
}

// round 8
// speedup vs baseline: 2.2156x; 1.0045x over previous
#include <cuda_runtime.h>
#include <cuda_bf16.h>
#include <cstdint>

#define NN    50000
#define EE    800000
#define IN_F  128
#define OUT_F 64
#define NH    4
#define HO    256   // NH*OUT_F
#define NEG_SLOPE 0.2f
#define BN_EPS 1e-5f

#define BM 128
#define BK 16

// ---------------- scratch (device globals; zero-init at load, self-cleaned) --
__device__ float        g_h     [(size_t)NN * HO];     // node_feats @ W_fc
__device__ float        g_gres  [(size_t)NN * HO];     // node_feats @ gat_res_w
__device__ float        g_y0    [(size_t)NN * OUT_F];  // relu(node@res_w + res_b)
__device__ float        g_ybuf  [(size_t)NN * OUT_F];  // pre-BN y
__device__ float        g_el    [NN * NH];
__device__ float        g_er    [NN * NH];
__device__ int          g_deg   [NN];                  // self-cleaned (by scan)
__device__ int          g_off   [NN];                  // csr offsets
__device__ int          g_cursor[NN];                  // self-cleaned (by agg)
__device__ int          g_esrc  [EE];                  // dst-sorted src indices
__device__ float        g_bnsum [OUT_F];               // self-cleaned
__device__ float        g_bnsq  [OUT_F];               // self-cleaned
__device__ float        g_scale [OUT_F];
__device__ float        g_shift [OUT_F];

// ---------------- packed f32x2 helpers (sm_103a FFMA2 — PTX-only) -----------
__device__ __forceinline__ void ffma2(unsigned long long& c,
                                      unsigned long long a,
                                      unsigned long long b) {
    asm("fma.rn.f32x2 %0, %1, %2, %0;" : "+l"(c) : "l"(a), "l"(b));
}
__device__ __forceinline__ unsigned long long pack2(float x) {
    unsigned long long r;
    asm("mov.b64 %0, {%1, %1};" : "=l"(r) : "f"(x));
    return r;
}

// ---------------- Kernel 1: three GEMMs in one + fused el/er epilogue -------
// Block tile 128 (M) x 64 (N). 256 threads = 8 warps.
//   warp w owns cols [w*8, w*8+8)  (warp-uniform B -> LDS broadcast)
//   lane l owns rows lane*4..lane*4+3 (same rows in every warp)
// grid.x = ceil(NN/128) = 391, grid.y = 9:
//   ct 0-3: Wfc head ct (cols ct*64..)    ct 4-7: gres (cols (ct-4)*64..)
//   ct 8:   res (cols 0-63)
// FFMA2 pairs run along N: B pairs load directly as u64 from smem.
__global__ void __launch_bounds__(256)
gemm_kernel(const float* __restrict__ A,
            const float* __restrict__ Wfc,
            const float* __restrict__ Wgres,
            const float* __restrict__ Wres,
            const float* __restrict__ res_b,
            const float* __restrict__ attn_l,
            const float* __restrict__ attn_r)
{
    const int ct = blockIdx.y;
    const float* B;
    int ldb, colbase, mode;
    if (ct < 4)      { B = Wfc;   ldb = HO;    colbase = ct * 64;       mode = 0; }
    else if (ct < 8) { B = Wgres; ldb = HO;    colbase = (ct - 4) * 64; mode = 1; }
    else             { B = Wres;  ldb = OUT_F; colbase = 0;             mode = 2; }

    __shared__ union {
        struct {
            float As[BK][BM + 4];   // [k][m], 528B rows (16B aligned)
            float Bs[BK][64 + 4];   // [k][n], 272B rows (16B aligned)
        } g;
        struct {
            float el[8][BM];
            float er[8][BM];
        } r;
    } S;

    const int t    = threadIdx.x;
    const int lane = t & 31;
    const int w    = t >> 5;          // warp 0..7
    const int wc   = w * 8;           // this warp's col group
    const int m0   = lane * 4;        // this thread's 4 rows (within tile)
    const int row0 = blockIdx.x * BM;

    // A load mapping: row = t&127, kq = (t>>7)*8
    const int ar  = t & 127;
    const int akq = (t >> 7) * 8;
    // B load mapping: kr = t>>4 (0..15), cq = (t&15)*4
    const int bkr = t >> 4;
    const int bcq = (t & 15) * 4;

    unsigned long long acc[4][4];     // acc[r][jp]: row m0+r, cols wc+2jp, wc+2jp+1
#pragma unroll
    for (int r = 0; r < 4; r++)
#pragma unroll
        for (int j = 0; j < 4; j++) acc[r][j] = 0ull;

    float4 av0, av1, bv;
    {   // prefetch tile 0
        int grow = row0 + ar;
        if (grow < NN) {
            const float4* ap = reinterpret_cast<const float4*>(A + (size_t)grow * IN_F + akq);
            av0 = ap[0]; av1 = ap[1];
        } else { av0 = make_float4(0.f,0.f,0.f,0.f); av1 = av0; }
        bv = *reinterpret_cast<const float4*>(B + (size_t)bkr * ldb + colbase + bcq);
    }

    for (int kt = 0; kt < IN_F / BK; kt++) {
        S.g.As[akq + 0][ar] = av0.x; S.g.As[akq + 1][ar] = av0.y;
        S.g.As[akq + 2][ar] = av0.z; S.g.As[akq + 3][ar] = av0.w;
        S.g.As[akq + 4][ar] = av1.x; S.g.As[akq + 5][ar] = av1.y;
        S.g.As[akq + 6][ar] = av1.z; S.g.As[akq + 7][ar] = av1.w;
        *reinterpret_cast<float4*>(&S.g.Bs[bkr][bcq]) = bv;
        __syncthreads();

        if (kt + 1 < IN_F / BK) {     // prefetch next
            int k0 = (kt + 1) * BK;
            int grow = row0 + ar;
            if (grow < NN) {
                const float4* ap = reinterpret_cast<const float4*>(A + (size_t)grow * IN_F + k0 + akq);
                av0 = ap[0]; av1 = ap[1];
            } else { av0 = make_float4(0.f,0.f,0.f,0.f); av1 = av0; }
            bv = *reinterpret_cast<const float4*>(B + (size_t)(k0 + bkr) * ldb + colbase + bcq);
        }

#pragma unroll
        for (int kk = 0; kk < BK; kk++) {
            float4 a4 = *reinterpret_cast<const float4*>(&S.g.As[kk][m0]);
            ulonglong2 b01 = *reinterpret_cast<const ulonglong2*>(&S.g.Bs[kk][wc]);      // {c0,c1},{c2,c3}
            ulonglong2 b23 = *reinterpret_cast<const ulonglong2*>(&S.g.Bs[kk][wc + 4]);  // {c4,c5},{c6,c7}
            unsigned long long ap0 = pack2(a4.x), ap1 = pack2(a4.y),
                               ap2 = pack2(a4.z), ap3 = pack2(a4.w);
            ffma2(acc[0][0], ap0, b01.x); ffma2(acc[0][1], ap0, b01.y);
            ffma2(acc[0][2], ap0, b23.x); ffma2(acc[0][3], ap0, b23.y);
            ffma2(acc[1][0], ap1, b01.x); ffma2(acc[1][1], ap1, b01.y);
            ffma2(acc[1][2], ap1, b23.x); ffma2(acc[1][3], ap1, b23.y);
            ffma2(acc[2][0], ap2, b01.x); ffma2(acc[2][1], ap2, b01.y);
            ffma2(acc[2][2], ap2, b23.x); ffma2(acc[2][3], ap2, b23.y);
            ffma2(acc[3][0], ap3, b01.x); ffma2(acc[3][1], ap3, b01.y);
            ffma2(acc[3][2], ap3, b23.x); ffma2(acc[3][3], ap3, b23.y);
        }
        __syncthreads();
    }

    // ---------------- store outputs (acc[r] = cols wc..wc+7 contiguous) ------
#pragma unroll
    for (int r = 0; r < 4; r++) {
        int grow = row0 + m0 + r;
        if (grow >= NN) continue;
        const float* c = reinterpret_cast<const float*>(acc[r]);
        float4 v0 = make_float4(c[0], c[1], c[2], c[3]);
        float4 v1 = make_float4(c[4], c[5], c[6], c[7]);
        int gcol = colbase + wc;
        if (mode == 0) {
            *reinterpret_cast<float4*>(g_h + (size_t)grow * HO + gcol)     = v0;
            *reinterpret_cast<float4*>(g_h + (size_t)grow * HO + gcol + 4) = v1;
        } else if (mode == 1) {
            *reinterpret_cast<float4*>(g_gres + (size_t)grow * HO + gcol)     = v0;
            *reinterpret_cast<float4*>(g_gres + (size_t)grow * HO + gcol + 4) = v1;
        } else {
            const float4 rb0 = *reinterpret_cast<const float4*>(res_b + gcol);
            const float4 rb1 = *reinterpret_cast<const float4*>(res_b + gcol + 4);
            v0.x = fmaxf(v0.x + rb0.x, 0.f); v0.y = fmaxf(v0.y + rb0.y, 0.f);
            v0.z = fmaxf(v0.z + rb0.z, 0.f); v0.w = fmaxf(v0.w + rb0.w, 0.f);
            v1.x = fmaxf(v1.x + rb1.x, 0.f); v1.y = fmaxf(v1.y + rb1.y, 0.f);
            v1.z = fmaxf(v1.z + rb1.z, 0.f); v1.w = fmaxf(v1.w + rb1.w, 0.f);
            *reinterpret_cast<float4*>(g_y0 + (size_t)grow * OUT_F + gcol)     = v0;
            *reinterpret_cast<float4*>(g_y0 + (size_t)grow * OUT_F + gcol + 4) = v1;
        }
    }

    // ---------------- fused el/er epilogue (mode 0: ct == head) --------------
    if (mode == 0) {
        const int head = ct;
        float al[8], arr[8];
        {
            float4 a0 = *reinterpret_cast<const float4*>(attn_l + head * OUT_F + wc);
            float4 a1 = *reinterpret_cast<const float4*>(attn_l + head * OUT_F + wc + 4);
            al[0]=a0.x; al[1]=a0.y; al[2]=a0.z; al[3]=a0.w; al[4]=a1.x; al[5]=a1.y; al[6]=a1.z; al[7]=a1.w;
            float4 r0 = *reinterpret_cast<const float4*>(attn_r + head * OUT_F + wc);
            float4 r1 = *reinterpret_cast<const float4*>(attn_r + head * OUT_F + wc + 4);
            arr[0]=r0.x; arr[1]=r0.y; arr[2]=r0.z; arr[3]=r0.w; arr[4]=r1.x; arr[5]=r1.y; arr[6]=r1.z; arr[7]=r1.w;
        }
        __syncthreads();   // done with As/Bs; union reuse
#pragma unroll
        for (int r = 0; r < 4; r++) {
            const float* c = reinterpret_cast<const float*>(acc[r]);
            float el = 0.f, er = 0.f;
#pragma unroll
            for (int j = 0; j < 8; j++) {
                el = fmaf(c[j], al[j],  el);
                er = fmaf(c[j], arr[j], er);
            }
            S.r.el[w][m0 + r] = el;
            S.r.er[w][m0 + r] = er;
        }
        __syncthreads();
        if (t < BM) {
            int grow = row0 + t;
            if (grow < NN) {
                float el = 0.f, er = 0.f;
#pragma unroll
                for (int ww = 0; ww < 8; ww++) { el += S.r.el[ww][t]; er += S.r.er[ww][t]; }
                g_el[grow * NH + head] = el;
                g_er[grow * NH + head] = er;
            }
        }
    }
}

// ---------------- Kernel 3a: degree histogram --------------------------------
__global__ void hist_kernel(const int* __restrict__ dst)
{
    int e = blockIdx.x * blockDim.x + threadIdx.x;
    if (e >= EE) return;
    atomicAdd(&g_deg[dst[e]], 1);
}

// ---------------- Kernel 3b: exclusive scan (1 block) + zero g_deg ----------
__global__ void scan_kernel()
{
    const int tid = threadIdx.x;   // 1024 threads
    __shared__ int wsum[32];
    __shared__ int s_carry;
    if (tid == 0) s_carry = 0;
    __syncthreads();
    for (int base = 0; base < NN; base += 1024) {
        int i = base + tid;
        int v = (i < NN) ? g_deg[i] : 0;
        if (i < NN) g_deg[i] = 0;            // self-clean
        int incl = v;
#pragma unroll
        for (int o = 1; o < 32; o <<= 1) {
            int t = __shfl_up_sync(0xffffffffu, incl, o);
            if ((tid & 31) >= o) incl += t;
        }
        if ((tid & 31) == 31) wsum[tid >> 5] = incl;
        __syncthreads();
        if (tid < 32) {
            int w = wsum[tid];
            int wi = w;
#pragma unroll
            for (int o = 1; o < 32; o <<= 1) {
                int t = __shfl_up_sync(0xffffffffu, wi, o);
                if (tid >= o) wi += t;
            }
            wsum[tid] = wi - w;              // exclusive warp offset
        }
        __syncthreads();
        incl += wsum[tid >> 5];
        int carry = s_carry;
        if (i < NN) g_off[i] = carry + incl - v;
        __syncthreads();                      // all reads of s_carry done
        if (tid == 1023) s_carry = carry + incl;
        __syncthreads();
    }
}

// ---------------- Kernel 3c: scatter src into dst-sorted order ---------------
__global__ void scatter_kernel(const int* __restrict__ src,
                               const int* __restrict__ dst)
{
    int e = blockIdx.x * blockDim.x + threadIdx.x;
    if (e >= EE) return;
    int d = dst[e];
    int p = g_off[d] + atomicAdd(&g_cursor[d], 1);
    g_esrc[p] = src[e];
}

// ---------------- Kernel 4: fused per-dst softmax + aggregation + epilogue --
// warp per dst node; 8 warps/block; grid = NN/8 (exact: 50000 = 6250*8)
__global__ void agg_kernel(const float* __restrict__ gat_bias,
                           const float* __restrict__ conv_w,
                           const float* __restrict__ conv_b)
{
    const int lane = threadIdx.x & 31;
    const int w    = threadIdx.x >> 5;      // 0..7
    const int n    = blockIdx.x * 8 + w;

    const int off = g_off[n];
    const int deg = g_cursor[n];

    const float4 er4 = *reinterpret_cast<const float4*>(g_er + n * 4);

    // pass 1: per-head max over incoming edges
    float m0 = -1e30f, m1 = -1e30f, m2 = -1e30f, m3 = -1e30f;
    for (int base = 0; base < deg; base += 32) {
        int e = base + lane;
        int s = (e < deg) ? g_esrc[off + e] : 0;
        float4 elv = *reinterpret_cast<const float4*>(g_el + s * 4);
        float l0 = elv.x + er4.x; l0 = (l0 >= 0.f) ? l0 : NEG_SLOPE * l0;
        float l1 = elv.y + er4.y; l1 = (l1 >= 0.f) ? l1 : NEG_SLOPE * l1;
        float l2 = elv.z + er4.z; l2 = (l2 >= 0.f) ? l2 : NEG_SLOPE * l2;
        float l3 = elv.w + er4.w; l3 = (l3 >= 0.f) ? l3 : NEG_SLOPE * l3;
        if (e < deg) {
            m0 = fmaxf(m0, l0); m1 = fmaxf(m1, l1);
            m2 = fmaxf(m2, l2); m3 = fmaxf(m3, l3);
        }
    }
#pragma unroll
    for (int o = 16; o; o >>= 1) {
        m0 = fmaxf(m0, __shfl_xor_sync(0xffffffffu, m0, o));
        m1 = fmaxf(m1, __shfl_xor_sync(0xffffffffu, m1, o));
        m2 = fmaxf(m2, __shfl_xor_sync(0xffffffffu, m2, o));
        m3 = fmaxf(m3, __shfl_xor_sync(0xffffffffu, m3, o));
    }

    // pass 2: exp, segment sum, weighted aggregation (in registers)
    float s0 = 0.f, s1 = 0.f, s2 = 0.f, s3 = 0.f;
    float4 acc0 = make_float4(0.f, 0.f, 0.f, 0.f);
    float4 acc1 = make_float4(0.f, 0.f, 0.f, 0.f);
    for (int base = 0; base < deg; base += 32) {
        int cnt = min(32, deg - base);
        int e = base + lane;
        int sidx = (e < deg) ? g_esrc[off + e] : 0;
        float4 elv = *reinterpret_cast<const float4*>(g_el + sidx * 4);
        float l0 = elv.x + er4.x; l0 = (l0 >= 0.f) ? l0 : NEG_SLOPE * l0;
        float l1 = elv.y + er4.y; l1 = (l1 >= 0.f) ? l1 : NEG_SLOPE * l1;
        float l2 = elv.z + er4.z; l2 = (l2 >= 0.f) ? l2 : NEG_SLOPE * l2;
        float l3 = elv.w + er4.w; l3 = (l3 >= 0.f) ? l3 : NEG_SLOPE * l3;
        float a0 = (e < deg) ? __expf(l0 - m0) : 0.f;
        float a1 = (e < deg) ? __expf(l1 - m1) : 0.f;
        float a2 = (e < deg) ? __expf(l2 - m2) : 0.f;
        float a3 = (e < deg) ? __expf(l3 - m3) : 0.f;
        s0 += a0; s1 += a1; s2 += a2; s3 += a3;

        for (int ee = 0; ee < cnt; ee++) {
            int   sv = __shfl_sync(0xffffffffu, sidx, ee);
            float b0 = __shfl_sync(0xffffffffu, a0, ee);
            float b1 = __shfl_sync(0xffffffffu, a1, ee);
            float b2 = __shfl_sync(0xffffffffu, a2, ee);
            float b3 = __shfl_sync(0xffffffffu, a3, ee);
            float w0 = (lane < 16) ? b0 : b1;
            float w1 = (lane < 16) ? b2 : b3;
            const float4* hrow = reinterpret_cast<const float4*>(g_h + (size_t)sv * HO);
            float4 h0 = hrow[lane];
            float4 h1 = hrow[lane + 32];
            acc0.x = fmaf(w0, h0.x, acc0.x); acc0.y = fmaf(w0, h0.y, acc0.y);
            acc0.z = fmaf(w0, h0.z, acc0.z); acc0.w = fmaf(w0, h0.w, acc0.w);
            acc1.x = fmaf(w1, h1.x, acc1.x); acc1.y = fmaf(w1, h1.y, acc1.y);
            acc1.z = fmaf(w1, h1.z, acc1.z); acc1.w = fmaf(w1, h1.w, acc1.w);
        }
    }
#pragma unroll
    for (int o = 16; o; o >>= 1) {
        s0 += __shfl_xor_sync(0xffffffffu, s0, o);
        s1 += __shfl_xor_sync(0xffffffffu, s1, o);
        s2 += __shfl_xor_sync(0xffffffffu, s2, o);
        s3 += __shfl_xor_sync(0xffffffffu, s3, o);
    }

    // normalize + gat residual + bias + relu + conv head-merge
    const float invA = 1.f / (((lane < 16) ? s0 : s1) + 1e-16f);
    const float invB = 1.f / (((lane < 16) ? s2 : s3) + 1e-16f);
    const int hA = (lane < 16) ? 0 : 1;
    const int hB = (lane < 16) ? 2 : 3;
    const int c4 = (lane & 15) * 4;
    const float4 gA = *reinterpret_cast<const float4*>(g_gres + (size_t)n * HO + hA * OUT_F + c4);
    const float4 gB = *reinterpret_cast<const float4*>(g_gres + (size_t)n * HO + hB * OUT_F + c4);
    const float4 bA = *reinterpret_cast<const float4*>(gat_bias + hA * OUT_F + c4);
    const float4 bB = *reinterpret_cast<const float4*>(gat_bias + hB * OUT_F + c4);
    const float cwA = conv_w[hA], cwB = conv_w[hB];

    float4 part;
    part.x = fmaxf(acc0.x * invA + gA.x + bA.x, 0.f) * cwA + fmaxf(acc1.x * invB + gB.x + bB.x, 0.f) * cwB;
    part.y = fmaxf(acc0.y * invA + gA.y + bA.y, 0.f) * cwA + fmaxf(acc1.y * invB + gB.y + bB.y, 0.f) * cwB;
    part.z = fmaxf(acc0.z * invA + gA.z + bA.z, 0.f) * cwA + fmaxf(acc1.z * invB + gB.z + bB.z, 0.f) * cwB;
    part.w = fmaxf(acc0.w * invA + gA.w + bA.w, 0.f) * cwA + fmaxf(acc1.w * invB + gB.w + bB.w, 0.f) * cwB;
    part.x += __shfl_xor_sync(0xffffffffu, part.x, 16);
    part.y += __shfl_xor_sync(0xffffffffu, part.y, 16);
    part.z += __shfl_xor_sync(0xffffffffu, part.z, 16);
    part.w += __shfl_xor_sync(0xffffffffu, part.w, 16);

    __shared__ float shs[8][68];
    __shared__ float shq[8][68];
    if (lane < 16) {
        const float4 y0v = *reinterpret_cast<const float4*>(g_y0 + (size_t)n * OUT_F + c4);
        const float cb = conv_b[0];
        float4 y4;
        y4.x = part.x + cb + y0v.x;
        y4.y = part.y + cb + y0v.y;
        y4.z = part.z + cb + y0v.z;
        y4.w = part.w + cb + y0v.w;
        *reinterpret_cast<float4*>(g_ybuf + (size_t)n * OUT_F + c4) = y4;
        *reinterpret_cast<float4*>(&shs[w][c4]) = y4;
        float4 q = make_float4(y4.x * y4.x, y4.y * y4.y, y4.z * y4.z, y4.w * y4.w);
        *reinterpret_cast<float4*>(&shq[w][c4]) = q;
    }
    if (lane == 0) g_cursor[n] = 0;          // self-clean for next launch
    __syncthreads();

    const int t = threadIdx.x;
    if (t < 64) {
        float sv = 0.f;
#pragma unroll
        for (int r = 0; r < 8; r++) sv += shs[r][t];
        atomicAdd(&g_bnsum[t], sv);
    } else if (t >= 128 && t < 192) {
        int d = t - 128;
        float qv = 0.f;
#pragma unroll
        for (int r = 0; r < 8; r++) qv += shq[r][d];
        atomicAdd(&g_bnsq[d], qv);
    }
}

// ---------------- Kernel 5: BN stats -> scale/shift (+ self-clean) ----------
__global__ void bn_stats_kernel(const float* __restrict__ gamma,
                                const float* __restrict__ beta)
{
    int d = threadIdx.x;
    if (d >= OUT_F) return;
    float mean = g_bnsum[d] / (float)NN;
    float var  = g_bnsq[d] / (float)NN - mean * mean;
    float rstd = rsqrtf(var + BN_EPS);
    float sc = gamma[d] * rstd;
    g_scale[d] = sc;
    g_shift[d] = beta[d] - mean * sc;
    g_bnsum[d] = 0.f;   // self-clean
    g_bnsq[d]  = 0.f;
}

// ---------------- Kernel 6: normalize -> d_out -------------------------------
__global__ void bn_apply_kernel(float* __restrict__ out)
{
    int i = blockIdx.x * blockDim.x + threadIdx.x;
    if (i >= NN * OUT_F) return;
    int d = i & (OUT_F - 1);
    out[i] = g_ybuf[i] * g_scale[d] + g_shift[d];
}

// ---------------- launch -----------------------------------------------------
extern "C" void kernel_launch(void* const* d_in, const int* in_sizes, int n_in,
                              void* d_out, int out_size)
{
    const float* node_feats = (const float*)d_in[0];
    const float* W_fc       = (const float*)d_in[1];
    const float* attn_l     = (const float*)d_in[2];
    const float* attn_r     = (const float*)d_in[3];
    const float* gat_res_w  = (const float*)d_in[4];
    const float* gat_bias   = (const float*)d_in[5];
    const float* conv_w     = (const float*)d_in[6];
    const float* conv_b     = (const float*)d_in[7];
    const float* res_w      = (const float*)d_in[8];
    const float* res_b      = (const float*)d_in[9];
    const float* bn_gamma   = (const float*)d_in[10];
    const float* bn_beta    = (const float*)d_in[11];
    const int*   src        = (const int*)d_in[12];
    const int*   dst        = (const int*)d_in[13];
    float*       out        = (float*)d_out;

    // edge sort (independent of GEMM output)
    hist_kernel<<<(EE + 255) / 256, 256>>>(dst);
    scan_kernel<<<1, 1024>>>();
    scatter_kernel<<<(EE + 255) / 256, 256>>>(src, dst);

    // three GEMMs (+ fused el/er epilogue)
    {
        dim3 grid((NN + BM - 1) / BM, 9);
        gemm_kernel<<<grid, 256>>>(node_feats, W_fc, gat_res_w, res_w, res_b,
                                   attn_l, attn_r);
    }
    // fused softmax + aggregation + node epilogue + BN partials
    agg_kernel<<<NN / 8, 256>>>(gat_bias, conv_w, conv_b);
    // BN stats
    bn_stats_kernel<<<1, 64>>>(bn_gamma, bn_beta);
    // normalize
    bn_apply_kernel<<<(NN * OUT_F + 255) / 256, 256>>>(out);
}

// round 10
// speedup vs baseline: 2.2310x; 1.0070x over previous
#include <cuda_runtime.h>
#include <cuda_bf16.h>
#include <cstdint>

#define NN    50000
#define EE    800000
#define IN_F  128
#define OUT_F 64
#define NH    4
#define HO    256   // NH*OUT_F
#define NEG_SLOPE 0.2f
#define BN_EPS 1e-5f

#define BM 128
#define BK 16

// ---------------- scratch (device globals; zero-init at load, self-cleaned) --
__device__ float        g_h     [(size_t)NN * HO];     // node_feats @ W_fc
__device__ float        g_gres  [(size_t)NN * HO];     // node_feats @ gat_res_w
__device__ float        g_y0    [(size_t)NN * OUT_F];  // relu(node@res_w + res_b)
__device__ float        g_ybuf  [(size_t)NN * OUT_F];  // pre-BN y
__device__ float        g_el    [NN * NH];
__device__ float        g_er    [NN * NH];
__device__ int          g_deg   [NN];                  // self-cleaned (by scan)
__device__ int          g_off   [NN];                  // csr offsets
__device__ int          g_cursor[NN];                  // self-cleaned (by agg)
__device__ int          g_esrc  [EE];                  // dst-sorted src indices
__device__ float        g_bnsum [OUT_F];               // self-cleaned
__device__ float        g_bnsq  [OUT_F];               // self-cleaned
__device__ float        g_scale [OUT_F];
__device__ float        g_shift [OUT_F];

// ---------------- packed f32x2 helpers (sm_103a FFMA2 — PTX-only) -----------
__device__ __forceinline__ void ffma2(unsigned long long& c,
                                      unsigned long long a,
                                      unsigned long long b) {
    asm("fma.rn.f32x2 %0, %1, %2, %0;" : "+l"(c) : "l"(a), "l"(b));
}
__device__ __forceinline__ unsigned long long pack2(float x) {
    unsigned long long r;
    asm("mov.b64 %0, {%1, %1};" : "=l"(r) : "f"(x));
    return r;
}

// ---------------- Kernel 1: three GEMMs in one + fused el/er epilogue -------
// Block tile 128 (M) x 64 (N). 256 threads = 8 warps.
//   warp w owns rows [w*16, w*16+16) x ALL 64 cols (A-slice private per warp)
//   lane = rg*8+cg: rows w*16+rg*4..+3 ; cols {cg*4..+3} U {32+cg*4..+3}
// A LDS: 4 distinct 16B addrs (8-way bcast) = 1 wf; B LDS: 2x128B = 2 wf.
// grid.y = 9: ct 0-3 Wfc head ct | ct 4-7 gres | ct 8 res
__global__ void __launch_bounds__(256)
gemm_kernel(const float* __restrict__ A,
            const float* __restrict__ Wfc,
            const float* __restrict__ Wgres,
            const float* __restrict__ Wres,
            const float* __restrict__ res_b,
            const float* __restrict__ attn_l,
            const float* __restrict__ attn_r)
{
    const int ct = blockIdx.y;
    const float* B;
    int ldb, colbase, mode;
    if (ct < 4)      { B = Wfc;   ldb = HO;    colbase = ct * 64;       mode = 0; }
    else if (ct < 8) { B = Wgres; ldb = HO;    colbase = (ct - 4) * 64; mode = 1; }
    else             { B = Wres;  ldb = OUT_F; colbase = 0;             mode = 2; }

    __shared__ float As[BK][BM + 4];   // [k][m], 528B rows (16B aligned)
    __shared__ float Bs[BK][64 + 4];   // [k][n], 272B rows (16B aligned)

    const int t    = threadIdx.x;
    const int lane = t & 31;
    const int w    = t >> 5;           // warp 0..7
    const int rg   = lane >> 3;        // row group 0..3
    const int cg   = lane & 7;         // col group 0..7
    const int m0   = w * 16 + rg * 4;  // this thread's 4 rows (within tile)
    const int c0   = cg * 4;           // first col quad; second at c0+32
    const int row0 = blockIdx.x * BM;

    // A load mapping: row = t&127, kq = (t>>7)*8
    const int ar  = t & 127;
    const int akq = (t >> 7) * 8;
    // B load mapping: kr = t>>4 (0..15), cq = (t&15)*4
    const int bkr = t >> 4;
    const int bcq = (t & 15) * 4;

    // acc[r][0..1]: row m0+r, col pairs (c0,c0+1),(c0+2,c0+3)
    // acc[r][2..3]: row m0+r, col pairs (c0+32,c0+33),(c0+34,c0+35)
    unsigned long long acc[4][4];
#pragma unroll
    for (int r = 0; r < 4; r++)
#pragma unroll
        for (int j = 0; j < 4; j++) acc[r][j] = 0ull;

    float4 av0, av1, bv;
    {   // prefetch tile 0
        int grow = row0 + ar;
        if (grow < NN) {
            const float4* ap = reinterpret_cast<const float4*>(A + (size_t)grow * IN_F + akq);
            av0 = ap[0]; av1 = ap[1];
        } else { av0 = make_float4(0.f,0.f,0.f,0.f); av1 = av0; }
        bv = *reinterpret_cast<const float4*>(B + (size_t)bkr * ldb + colbase + bcq);
    }

    for (int kt = 0; kt < IN_F / BK; kt++) {
        As[akq + 0][ar] = av0.x; As[akq + 1][ar] = av0.y;
        As[akq + 2][ar] = av0.z; As[akq + 3][ar] = av0.w;
        As[akq + 4][ar] = av1.x; As[akq + 5][ar] = av1.y;
        As[akq + 6][ar] = av1.z; As[akq + 7][ar] = av1.w;
        *reinterpret_cast<float4*>(&Bs[bkr][bcq]) = bv;
        __syncthreads();

        if (kt + 1 < IN_F / BK) {     // prefetch next
            int k0 = (kt + 1) * BK;
            int grow = row0 + ar;
            if (grow < NN) {
                const float4* ap = reinterpret_cast<const float4*>(A + (size_t)grow * IN_F + k0 + akq);
                av0 = ap[0]; av1 = ap[1];
            } else { av0 = make_float4(0.f,0.f,0.f,0.f); av1 = av0; }
            bv = *reinterpret_cast<const float4*>(B + (size_t)(k0 + bkr) * ldb + colbase + bcq);
        }

#pragma unroll
        for (int kk = 0; kk < BK; kk++) {
            float4 a4 = *reinterpret_cast<const float4*>(&As[kk][m0]);          // 1 wf (bcast)
            ulonglong2 bL = *reinterpret_cast<const ulonglong2*>(&Bs[kk][c0]);      // 1 wf
            ulonglong2 bH = *reinterpret_cast<const ulonglong2*>(&Bs[kk][c0 + 32]); // 1 wf
            unsigned long long ap0 = pack2(a4.x), ap1 = pack2(a4.y),
                               ap2 = pack2(a4.z), ap3 = pack2(a4.w);
            ffma2(acc[0][0], ap0, bL.x); ffma2(acc[0][1], ap0, bL.y);
            ffma2(acc[0][2], ap0, bH.x); ffma2(acc[0][3], ap0, bH.y);
            ffma2(acc[1][0], ap1, bL.x); ffma2(acc[1][1], ap1, bL.y);
            ffma2(acc[1][2], ap1, bH.x); ffma2(acc[1][3], ap1, bH.y);
            ffma2(acc[2][0], ap2, bL.x); ffma2(acc[2][1], ap2, bL.y);
            ffma2(acc[2][2], ap2, bH.x); ffma2(acc[2][3], ap2, bH.y);
            ffma2(acc[3][0], ap3, bL.x); ffma2(acc[3][1], ap3, bL.y);
            ffma2(acc[3][2], ap3, bH.x); ffma2(acc[3][3], ap3, bH.y);
        }
        __syncthreads();
    }

    // ---------------- store outputs ------------------------------------------
#pragma unroll
    for (int r = 0; r < 4; r++) {
        int grow = row0 + m0 + r;
        if (grow >= NN) continue;
        const float* c = reinterpret_cast<const float*>(acc[r]);
        float4 v0 = make_float4(c[0], c[1], c[2], c[3]);   // cols c0..c0+3
        float4 v1 = make_float4(c[4], c[5], c[6], c[7]);   // cols c0+32..+35
        int gc0 = colbase + c0;
        int gc1 = colbase + c0 + 32;
        if (mode == 0) {
            *reinterpret_cast<float4*>(g_h + (size_t)grow * HO + gc0) = v0;
            *reinterpret_cast<float4*>(g_h + (size_t)grow * HO + gc1) = v1;
        } else if (mode == 1) {
            *reinterpret_cast<float4*>(g_gres + (size_t)grow * HO + gc0) = v0;
            *reinterpret_cast<float4*>(g_gres + (size_t)grow * HO + gc1) = v1;
        } else {
            const float4 rb0 = *reinterpret_cast<const float4*>(res_b + gc0);
            const float4 rb1 = *reinterpret_cast<const float4*>(res_b + gc1);
            v0.x = fmaxf(v0.x + rb0.x, 0.f); v0.y = fmaxf(v0.y + rb0.y, 0.f);
            v0.z = fmaxf(v0.z + rb0.z, 0.f); v0.w = fmaxf(v0.w + rb0.w, 0.f);
            v1.x = fmaxf(v1.x + rb1.x, 0.f); v1.y = fmaxf(v1.y + rb1.y, 0.f);
            v1.z = fmaxf(v1.z + rb1.z, 0.f); v1.w = fmaxf(v1.w + rb1.w, 0.f);
            *reinterpret_cast<float4*>(g_y0 + (size_t)grow * OUT_F + gc0) = v0;
            *reinterpret_cast<float4*>(g_y0 + (size_t)grow * OUT_F + gc1) = v1;
        }
    }

    // ---------------- fused el/er epilogue (mode 0: ct == head) --------------
    // Warps own disjoint rows -> reduce over cg lanes (bits 0-2) only.
    if (mode == 0) {
        const int head = ct;
        float al[8], arr[8];
        {
            float4 a0 = *reinterpret_cast<const float4*>(attn_l + head * OUT_F + c0);
            float4 a1 = *reinterpret_cast<const float4*>(attn_l + head * OUT_F + c0 + 32);
            al[0]=a0.x; al[1]=a0.y; al[2]=a0.z; al[3]=a0.w;
            al[4]=a1.x; al[5]=a1.y; al[6]=a1.z; al[7]=a1.w;
            float4 r0 = *reinterpret_cast<const float4*>(attn_r + head * OUT_F + c0);
            float4 r1 = *reinterpret_cast<const float4*>(attn_r + head * OUT_F + c0 + 32);
            arr[0]=r0.x; arr[1]=r0.y; arr[2]=r0.z; arr[3]=r0.w;
            arr[4]=r1.x; arr[5]=r1.y; arr[6]=r1.z; arr[7]=r1.w;
        }
#pragma unroll
        for (int r = 0; r < 4; r++) {
            const float* c = reinterpret_cast<const float*>(acc[r]);
            float el = 0.f, er = 0.f;
#pragma unroll
            for (int j = 0; j < 8; j++) {
                el = fmaf(c[j], al[j],  el);
                er = fmaf(c[j], arr[j], er);
            }
#pragma unroll
            for (int d = 1; d < 8; d <<= 1) {
                el += __shfl_xor_sync(0xffffffffu, el, d);
                er += __shfl_xor_sync(0xffffffffu, er, d);
            }
            if (cg == 0) {
                int grow = row0 + m0 + r;
                if (grow < NN) {
                    g_el[grow * NH + head] = el;
                    g_er[grow * NH + head] = er;
                }
            }
        }
    }
}

// ---------------- Kernel 3a: degree histogram --------------------------------
__global__ void hist_kernel(const int* __restrict__ dst)
{
    int e = blockIdx.x * blockDim.x + threadIdx.x;
    if (e >= EE) return;
    atomicAdd(&g_deg[dst[e]], 1);
}

// ---------------- Kernel 3b: exclusive scan (1 block) + zero g_deg ----------
__global__ void scan_kernel()
{
    const int tid = threadIdx.x;   // 1024 threads
    __shared__ int wsum[32];
    __shared__ int s_carry;
    if (tid == 0) s_carry = 0;
    __syncthreads();
    for (int base = 0; base < NN; base += 1024) {
        int i = base + tid;
        int v = (i < NN) ? g_deg[i] : 0;
        if (i < NN) g_deg[i] = 0;            // self-clean
        int incl = v;
#pragma unroll
        for (int o = 1; o < 32; o <<= 1) {
            int t = __shfl_up_sync(0xffffffffu, incl, o);
            if ((tid & 31) >= o) incl += t;
        }
        if ((tid & 31) == 31) wsum[tid >> 5] = incl;
        __syncthreads();
        if (tid < 32) {
            int w = wsum[tid];
            int wi = w;
#pragma unroll
            for (int o = 1; o < 32; o <<= 1) {
                int t = __shfl_up_sync(0xffffffffu, wi, o);
                if (tid >= o) wi += t;
            }
            wsum[tid] = wi - w;              // exclusive warp offset
        }
        __syncthreads();
        incl += wsum[tid >> 5];
        int carry = s_carry;
        if (i < NN) g_off[i] = carry + incl - v;
        __syncthreads();                      // all reads of s_carry done
        if (tid == 1023) s_carry = carry + incl;
        __syncthreads();
    }
}

// ---------------- Kernel 3c: scatter src into dst-sorted order ---------------
__global__ void scatter_kernel(const int* __restrict__ src,
                               const int* __restrict__ dst)
{
    int e = blockIdx.x * blockDim.x + threadIdx.x;
    if (e >= EE) return;
    int d = dst[e];
    int p = g_off[d] + atomicAdd(&g_cursor[d], 1);
    g_esrc[p] = src[e];
}

// ---------------- Kernel 4: fused per-dst softmax + aggregation + epilogue --
// warp per dst node; 8 warps/block; grid = NN/8 (exact: 50000 = 6250*8)
__global__ void agg_kernel(const float* __restrict__ gat_bias,
                           const float* __restrict__ conv_w,
                           const float* __restrict__ conv_b)
{
    const int lane = threadIdx.x & 31;
    const int w    = threadIdx.x >> 5;      // 0..7
    const int n    = blockIdx.x * 8 + w;

    const int off = g_off[n];
    const int deg = g_cursor[n];

    const float4 er4 = *reinterpret_cast<const float4*>(g_er + n * 4);

    // pass 1: per-head max over incoming edges
    float m0 = -1e30f, m1 = -1e30f, m2 = -1e30f, m3 = -1e30f;
    for (int base = 0; base < deg; base += 32) {
        int e = base + lane;
        int s = (e < deg) ? g_esrc[off + e] : 0;
        float4 elv = *reinterpret_cast<const float4*>(g_el + s * 4);
        float l0 = elv.x + er4.x; l0 = (l0 >= 0.f) ? l0 : NEG_SLOPE * l0;
        float l1 = elv.y + er4.y; l1 = (l1 >= 0.f) ? l1 : NEG_SLOPE * l1;
        float l2 = elv.z + er4.z; l2 = (l2 >= 0.f) ? l2 : NEG_SLOPE * l2;
        float l3 = elv.w + er4.w; l3 = (l3 >= 0.f) ? l3 : NEG_SLOPE * l3;
        if (e < deg) {
            m0 = fmaxf(m0, l0); m1 = fmaxf(m1, l1);
            m2 = fmaxf(m2, l2); m3 = fmaxf(m3, l3);
        }
    }
#pragma unroll
    for (int o = 16; o; o >>= 1) {
        m0 = fmaxf(m0, __shfl_xor_sync(0xffffffffu, m0, o));
        m1 = fmaxf(m1, __shfl_xor_sync(0xffffffffu, m1, o));
        m2 = fmaxf(m2, __shfl_xor_sync(0xffffffffu, m2, o));
        m3 = fmaxf(m3, __shfl_xor_sync(0xffffffffu, m3, o));
    }

    // pass 2: exp, segment sum, weighted aggregation (in registers)
    float s0 = 0.f, s1 = 0.f, s2 = 0.f, s3 = 0.f;
    float4 acc0 = make_float4(0.f, 0.f, 0.f, 0.f);
    float4 acc1 = make_float4(0.f, 0.f, 0.f, 0.f);
    for (int base = 0; base < deg; base += 32) {
        int cnt = min(32, deg - base);
        int e = base + lane;
        int sidx = (e < deg) ? g_esrc[off + e] : 0;
        float4 elv = *reinterpret_cast<const float4*>(g_el + sidx * 4);
        float l0 = elv.x + er4.x; l0 = (l0 >= 0.f) ? l0 : NEG_SLOPE * l0;
        float l1 = elv.y + er4.y; l1 = (l1 >= 0.f) ? l1 : NEG_SLOPE * l1;
        float l2 = elv.z + er4.z; l2 = (l2 >= 0.f) ? l2 : NEG_SLOPE * l2;
        float l3 = elv.w + er4.w; l3 = (l3 >= 0.f) ? l3 : NEG_SLOPE * l3;
        float a0 = (e < deg) ? __expf(l0 - m0) : 0.f;
        float a1 = (e < deg) ? __expf(l1 - m1) : 0.f;
        float a2 = (e < deg) ? __expf(l2 - m2) : 0.f;
        float a3 = (e < deg) ? __expf(l3 - m3) : 0.f;
        s0 += a0; s1 += a1; s2 += a2; s3 += a3;

        for (int ee = 0; ee < cnt; ee++) {
            int   sv = __shfl_sync(0xffffffffu, sidx, ee);
            float b0 = __shfl_sync(0xffffffffu, a0, ee);
            float b1 = __shfl_sync(0xffffffffu, a1, ee);
            float b2 = __shfl_sync(0xffffffffu, a2, ee);
            float b3 = __shfl_sync(0xffffffffu, a3, ee);
            float w0 = (lane < 16) ? b0 : b1;
            float w1 = (lane < 16) ? b2 : b3;
            const float4* hrow = reinterpret_cast<const float4*>(g_h + (size_t)sv * HO);
            float4 h0 = hrow[lane];
            float4 h1 = hrow[lane + 32];
            acc0.x = fmaf(w0, h0.x, acc0.x); acc0.y = fmaf(w0, h0.y, acc0.y);
            acc0.z = fmaf(w0, h0.z, acc0.z); acc0.w = fmaf(w0, h0.w, acc0.w);
            acc1.x = fmaf(w1, h1.x, acc1.x); acc1.y = fmaf(w1, h1.y, acc1.y);
            acc1.z = fmaf(w1, h1.z, acc1.z); acc1.w = fmaf(w1, h1.w, acc1.w);
        }
    }
#pragma unroll
    for (int o = 16; o; o >>= 1) {
        s0 += __shfl_xor_sync(0xffffffffu, s0, o);
        s1 += __shfl_xor_sync(0xffffffffu, s1, o);
        s2 += __shfl_xor_sync(0xffffffffu, s2, o);
        s3 += __shfl_xor_sync(0xffffffffu, s3, o);
    }

    // normalize + gat residual + bias + relu + conv head-merge
    const float invA = 1.f / (((lane < 16) ? s0 : s1) + 1e-16f);
    const float invB = 1.f / (((lane < 16) ? s2 : s3) + 1e-16f);
    const int hA = (lane < 16) ? 0 : 1;
    const int hB = (lane < 16) ? 2 : 3;
    const int c4 = (lane & 15) * 4;
    const float4 gA = *reinterpret_cast<const float4*>(g_gres + (size_t)n * HO + hA * OUT_F + c4);
    const float4 gB = *reinterpret_cast<const float4*>(g_gres + (size_t)n * HO + hB * OUT_F + c4);
    const float4 bA = *reinterpret_cast<const float4*>(gat_bias + hA * OUT_F + c4);
    const float4 bB = *reinterpret_cast<const float4*>(gat_bias + hB * OUT_F + c4);
    const float cwA = conv_w[hA], cwB = conv_w[hB];

    float4 part;
    part.x = fmaxf(acc0.x * invA + gA.x + bA.x, 0.f) * cwA + fmaxf(acc1.x * invB + gB.x + bB.x, 0.f) * cwB;
    part.y = fmaxf(acc0.y * invA + gA.y + bA.y, 0.f) * cwA + fmaxf(acc1.y * invB + gB.y + bB.y, 0.f) * cwB;
    part.z = fmaxf(acc0.z * invA + gA.z + bA.z, 0.f) * cwA + fmaxf(acc1.z * invB + gB.z + bB.z, 0.f) * cwB;
    part.w = fmaxf(acc0.w * invA + gA.w + bA.w, 0.f) * cwA + fmaxf(acc1.w * invB + gB.w + bB.w, 0.f) * cwB;
    part.x += __shfl_xor_sync(0xffffffffu, part.x, 16);
    part.y += __shfl_xor_sync(0xffffffffu, part.y, 16);
    part.z += __shfl_xor_sync(0xffffffffu, part.z, 16);
    part.w += __shfl_xor_sync(0xffffffffu, part.w, 16);

    __shared__ float shs[8][68];
    __shared__ float shq[8][68];
    if (lane < 16) {
        const float4 y0v = *reinterpret_cast<const float4*>(g_y0 + (size_t)n * OUT_F + c4);
        const float cb = conv_b[0];
        float4 y4;
        y4.x = part.x + cb + y0v.x;
        y4.y = part.y + cb + y0v.y;
        y4.z = part.z + cb + y0v.z;
        y4.w = part.w + cb + y0v.w;
        *reinterpret_cast<float4*>(g_ybuf + (size_t)n * OUT_F + c4) = y4;
        *reinterpret_cast<float4*>(&shs[w][c4]) = y4;
        float4 q = make_float4(y4.x * y4.x, y4.y * y4.y, y4.z * y4.z, y4.w * y4.w);
        *reinterpret_cast<float4*>(&shq[w][c4]) = q;
    }
    if (lane == 0) g_cursor[n] = 0;          // self-clean for next launch
    __syncthreads();

    const int t = threadIdx.x;
    if (t < 64) {
        float sv = 0.f;
#pragma unroll
        for (int r = 0; r < 8; r++) sv += shs[r][t];
        atomicAdd(&g_bnsum[t], sv);
    } else if (t >= 128 && t < 192) {
        int d = t - 128;
        float qv = 0.f;
#pragma unroll
        for (int r = 0; r < 8; r++) qv += shq[r][d];
        atomicAdd(&g_bnsq[d], qv);
    }
}

// ---------------- Kernel 5: BN stats -> scale/shift (+ self-clean) ----------
__global__ void bn_stats_kernel(const float* __restrict__ gamma,
                                const float* __restrict__ beta)
{
    int d = threadIdx.x;
    if (d >= OUT_F) return;
    float mean = g_bnsum[d] / (float)NN;
    float var  = g_bnsq[d] / (float)NN - mean * mean;
    float rstd = rsqrtf(var + BN_EPS);
    float sc = gamma[d] * rstd;
    g_scale[d] = sc;
    g_shift[d] = beta[d] - mean * sc;
    g_bnsum[d] = 0.f;   // self-clean
    g_bnsq[d]  = 0.f;
}

// ---------------- Kernel 6: normalize -> d_out -------------------------------
__global__ void bn_apply_kernel(float* __restrict__ out)
{
    int i = blockIdx.x * blockDim.x + threadIdx.x;
    if (i >= NN * OUT_F) return;
    int d = i & (OUT_F - 1);
    out[i] = g_ybuf[i] * g_scale[d] + g_shift[d];
}

// ---------------- launch -----------------------------------------------------
extern "C" void kernel_launch(void* const* d_in, const int* in_sizes, int n_in,
                              void* d_out, int out_size)
{
    const float* node_feats = (const float*)d_in[0];
    const float* W_fc       = (const float*)d_in[1];
    const float* attn_l     = (const float*)d_in[2];
    const float* attn_r     = (const float*)d_in[3];
    const float* gat_res_w  = (const float*)d_in[4];
    const float* gat_bias   = (const float*)d_in[5];
    const float* conv_w     = (const float*)d_in[6];
    const float* conv_b     = (const float*)d_in[7];
    const float* res_w      = (const float*)d_in[8];
    const float* res_b      = (const float*)d_in[9];
    const float* bn_gamma   = (const float*)d_in[10];
    const float* bn_beta    = (const float*)d_in[11];
    const int*   src        = (const int*)d_in[12];
    const int*   dst        = (const int*)d_in[13];
    float*       out        = (float*)d_out;

    // edge sort (independent of GEMM output)
    hist_kernel<<<(EE + 255) / 256, 256>>>(dst);
    scan_kernel<<<1, 1024>>>();
    scatter_kernel<<<(EE + 255) / 256, 256>>>(src, dst);

    // three GEMMs (+ fused el/er epilogue)
    {
        dim3 grid((NN + BM - 1) / BM, 9);
        gemm_kernel<<<grid, 256>>>(node_feats, W_fc, gat_res_w, res_w, res_b,
                                   attn_l, attn_r);
    }
    // fused softmax + aggregation + node epilogue + BN partials
    agg_kernel<<<NN / 8, 256>>>(gat_bias, conv_w, conv_b);
    // BN stats
    bn_stats_kernel<<<1, 64>>>(bn_gamma, bn_beta);
    // normalize
    bn_apply_kernel<<<(NN * OUT_F + 255) / 256, 256>>>(out);
}